// round 15
// baseline (speedup 1.0000x reference)
#include <cuda_runtime.h>
#include <cuda_fp16.h>
#include <math.h>
#include <stdint.h>

#define NVAR   100000
#define NCLS   400000
#define NEDG   600000
#define HDIM   128
#define NSTEPS 9

// ---------------- scratch (device globals) ----------------
__device__ __align__(16) __half g_hv [NVAR * HDIM];
__device__ __align__(16) __half g_hv2[NVAR * HDIM];
__device__ __align__(16) __half g_hc [NCLS * HDIM];
__device__ __align__(16) __half g_hc2[NCLS * HDIM];
__device__ __align__(16) __half g_t1 [NCLS * HDIM];
__device__ __align__(16) __half g_t2 [NCLS * HDIM];
__device__ __align__(16) __half g_m  [NCLS * HDIM];
__device__ __align__(16) __half g_cvh[NVAR * HDIM];   // fp16 shadow of c_v (post-relu)
__device__ __align__(16) __half g_cch[NCLS * HDIM];   // fp16 shadow of c_c
__device__ float g_cv [NVAR * HDIM];
__device__ float g_cc [NCLS * HDIM];
__device__ float g_z  [NCLS];
__device__ float    g_red[HDIM];
__device__ float    g_sum;
__device__ unsigned g_maxu;
// fp16 PAIRED fragment-major weights: eW1 | eW2 | eW3 | Wih' | Whh'
#define OFFH_E1  0
#define OFFH_E2  65536
#define OFFH_E3  131072
#define OFFH_WIH 196608
#define OFFH_WHH 327680
#define WH_N     458752
__device__ __align__(16) __half g_wh[WH_N];
__device__ float g_pb[1024];
#define PREP_N  459776
// CSR
__device__ int g_off[4][NCLS];
__device__ int g_csr[4][NEDG];
__device__ int g_cnt[NCLS];
__device__ int g_part[512];

// ---------------- helpers ----------------
__device__ __forceinline__ unsigned f2ord(float f) {
    unsigned b = __float_as_uint(f);
    return (b & 0x80000000u) ? ~b : (b | 0x80000000u);
}
__device__ __forceinline__ float ord2f(unsigned u) {
    unsigned b = (u & 0x80000000u) ? (u ^ 0x80000000u) : ~u;
    return __uint_as_float(b);
}
__device__ __forceinline__ float sigmoidf(float x) { return 1.0f / (1.0f + expf(-x)); }

__device__ __forceinline__ uint32_t pk2h(float a, float b) {
    __half2 h = __floats2half2_rn(a, b);
    return *(uint32_t*)&h;
}
__device__ __forceinline__ uint32_t smem_u32(const void* p) {
    uint32_t a;
    asm("{ .reg .u64 t; cvta.to.shared.u64 t, %1; cvt.u32.u64 %0, t; }" : "=r"(a) : "l"(p));
    return a;
}
__device__ __forceinline__ void cp_async16(uint32_t dst, const void* src, int srcbytes) {
    asm volatile("cp.async.cg.shared.global [%0], [%1], 16, %2;"
                 :: "r"(dst), "l"(src), "r"(srcbytes) : "memory");
}
__device__ __forceinline__ void cp_commit() {
    asm volatile("cp.async.commit_group;" ::: "memory");
}
__device__ __forceinline__ void cp_wait(int rem) {
    if (rem >= 1) asm volatile("cp.async.wait_group 1;" ::: "memory");
    else          asm volatile("cp.async.wait_group 0;" ::: "memory");
}
__device__ __forceinline__ void mma_f16(float* c, const uint32_t* a, uint32_t b0, uint32_t b1) {
    asm volatile(
        "mma.sync.aligned.m16n8k16.row.col.f32.f16.f16.f32 "
        "{%0,%1,%2,%3}, {%4,%5,%6,%7}, {%8,%9}, {%0,%1,%2,%3};"
        : "+f"(c[0]), "+f"(c[1]), "+f"(c[2]), "+f"(c[3])
        : "r"(a[0]), "r"(a[1]), "r"(a[2]), "r"(a[3]), "r"(b0), "r"(b1));
}

// ---------------- fused weight prep: fp16 PAIRED fragment-major ----------------
__global__ void prep_all(const float* __restrict__ eW1, const float* __restrict__ eW2,
                         const float* __restrict__ eW3, const float* __restrict__ Wih,
                         const float* __restrict__ Whh, const float* __restrict__ bih,
                         const float* __restrict__ bhh,
                         __half* __restrict__ wh, float* __restrict__ pbo)
{
    int i = blockIdx.x * blockDim.x + threadIdx.x;
    if (i >= PREP_N) return;
    if (i < 196608) {               // eW1|eW2|eW3
        const float* src = (i < 65536) ? eW1 : (i < 131072) ? eW2 : eW3;
        int base = (i < 65536) ? OFFH_E1 : (i < 131072) ? OFFH_E2 : OFFH_E3;
        int j = i & 65535;
        int etype = j >> 14;
        int rem = j & 16383;
        int n = rem >> 7, k = rem & 127;
        int uidx = ((k >> 4) * 8 + (n >> 4)) * 128 + ((n & 7) * 4 + ((k & 7) >> 1)) * 4
                   + ((n >> 3) & 1) * 2 + ((k >> 3) & 1);
        wh[base + (etype << 14) + uidx * 2 + (k & 1)] = __float2half_rn(src[j]);
    } else if (i < 458752) {        // Wih' | Whh'
        int j = i - 196608;
        const float* src = (j < 131072) ? Wih : Whh;
        int base = (j < 131072) ? OFFH_WIH : OFFH_WHH;
        j &= 131071;
        int rel = j >> 16;
        int rem = j & 65535;
        int r_old = rem >> 7, k = rem & 127;
        int gate = r_old >> 7, f = r_old & 127;
        int rn = (f << 2) | gate;
        int uidx = ((k >> 4) * 32 + (rn >> 4)) * 128 + ((rn & 7) * 4 + ((k & 7) >> 1)) * 4
                   + ((rn >> 3) & 1) * 2 + ((k >> 3) & 1);
        wh[base + (rel << 16) + uidx * 2 + (k & 1)] = __float2half_rn(src[j]);
    } else {                        // permuted bias sum (fp32)
        int j = i - 458752;
        int rel = j >> 9;
        int r_old = j & 511;
        int gate = r_old >> 7, f = r_old & 127;
        pbo[(rel << 9) + (f << 2) + gate] = bih[j] + bhh[j];
    }
}

// ---------------- CSR build kernels ----------------
__global__ void hist_k(const int* __restrict__ dst, int* __restrict__ cnt, int E) {
    int i = blockIdx.x * blockDim.x + threadIdx.x;
    if (i < E) atomicAdd(&cnt[dst[i]], 1);
}
__global__ void scan1_k(const int* __restrict__ cnt, int* __restrict__ off,
                        int* __restrict__ part, int N) {
    __shared__ int s[1024];
    int i = blockIdx.x * 1024 + threadIdx.x;
    int v = (i < N) ? cnt[i] : 0;
    s[threadIdx.x] = v;
    __syncthreads();
    for (int d = 1; d < 1024; d <<= 1) {
        int t = (threadIdx.x >= d) ? s[threadIdx.x - d] : 0;
        __syncthreads();
        s[threadIdx.x] += t;
        __syncthreads();
    }
    if (i < N) off[i] = s[threadIdx.x] - v;
    if (threadIdx.x == 1023) part[blockIdx.x] = s[1023];
}
__global__ void scan2_k(int* __restrict__ part, int NB) {
    __shared__ int s[512];
    int v = (threadIdx.x < NB) ? part[threadIdx.x] : 0;
    s[threadIdx.x] = v;
    __syncthreads();
    for (int d = 1; d < 512; d <<= 1) {
        int t = (threadIdx.x >= d) ? s[threadIdx.x - d] : 0;
        __syncthreads();
        s[threadIdx.x] += t;
        __syncthreads();
    }
    if (threadIdx.x < NB) part[threadIdx.x] = s[threadIdx.x] - v;
}
__global__ void scan3_k(int* __restrict__ off, const int* __restrict__ part, int N) {
    int i = blockIdx.x * 1024 + threadIdx.x;
    if (i < N) off[i] += part[blockIdx.x];
}
__global__ void fill_k(const int* __restrict__ src, const int* __restrict__ dst,
                       int* __restrict__ off, int* __restrict__ csr, int E) {
    int i = blockIdx.x * blockDim.x + threadIdx.x;
    if (i >= E) return;
    int p = atomicAdd(&off[dst[i]], 1);
    csr[p] = src[i];
}

// ---------------- init ----------------
__global__ void init_embed(const int* __restrict__ x, const float* __restrict__ embed,
                           __half* __restrict__ h, float* __restrict__ c,
                           __half* __restrict__ ch, int n) {
    int i = blockIdx.x * blockDim.x + threadIdx.x;
    if (i >= n * HDIM) return;
    int node = i >> 7, col = i & 127;
    float v = embed[x[node] * HDIM + col];
    h[i]  = __float2half_rn(v);
    c[i]  = v;
    ch[i] = __float2half_rn(v);
}

// ============ DUAL-etype fused 3-layer MLP, fp16 IN, paired-B, 3-stage pipeline ============
__global__ void __launch_bounds__(256, 2)
mlp3_dual(const __half* __restrict__ X,
          const __half* __restrict__ Wa1, const __half* __restrict__ Wa2,
          const __half* __restrict__ Wa3,
          const __half* __restrict__ Wb1, const __half* __restrict__ Wb2,
          const __half* __restrict__ Wb3,
          const float* __restrict__ Ba1, const float* __restrict__ Ba2,
          const float* __restrict__ Ba3,
          const float* __restrict__ Bb1, const float* __restrict__ Bb2,
          const float* __restrict__ Bb3,
          __half* __restrict__ Ya, __half* __restrict__ Yb, int N)
{
    extern __shared__ uint32_t smu[];
    uint32_t* Xs0 = smu;                  // 8192
    uint32_t* Xs1 = smu + 8192;           // 8192
    uint32_t* Wc  = smu + 16384;          // 3*2048
    float*    sb  = (float*)(smu + 22528); // 768

    const int tid    = threadIdx.x;
    const int wid    = tid >> 5;
    const int lane   = tid & 31;
    const int warp_m = wid & 3;
    const int warp_n = wid >> 2;
    const int gid    = lane >> 2;
    const int thid   = lane & 3;
    const int row0   = blockIdx.x << 7;

    const uint32_t wcaddr = smem_u32(Wc);

    if (tid < 128) {
        sb[tid]       = Ba1[tid];
        sb[128 + tid] = Ba2[tid];
        sb[256 + tid] = Ba3[tid];
        sb[384 + tid] = Bb1[tid];
        sb[512 + tid] = Bb2[tid];
        sb[640 + tid] = Bb3[tid];
    }

    auto issueW = [&](int g, int st) {
        const __half* Wl =
            (g < 12) ? ((g < 4) ? Wa1 : (g < 8) ? Wa2 : Wa3)
                     : ((g < 16) ? Wb1 : (g < 20) ? Wb2 : Wb3);
        Wl += (size_t)(g & 3) * 4096;
#pragma unroll
        for (int it = 0; it < 2; it++) {
            int idx = it * 256 + tid;
            cp_async16(wcaddr + (uint32_t)(st * 2048 + idx * 4) * 4u, Wl + idx * 8, 16);
        }
        cp_commit();
    };

    issueW(0, 0);
    issueW(1, 1);

    // prologue: X (fp16 row-major) -> fragments in Xs0 (no conversion needed)
#pragma unroll
    for (int it = 0; it < 8; it++) {
        int idx = it * 256 + tid;      // 0..2047
        int r   = idx & 127;
        int c8  = idx >> 7;            // 0..15
        int gk  = c8 << 3;             // 8 halfs per load
        int grow = row0 + r;
        uint4 xv = make_uint4(0u, 0u, 0u, 0u);
        if (grow < N) xv = *(const uint4*)(X + (size_t)grow * 128 + gk);
        int q16 = gk >> 4;
        int kh8 = (gk >> 3) & 1;
        int grp = r >> 4;
        int gd  = r & 7;
        int mh  = (r >> 3) & 1;
        int reg = mh + 2 * kh8;
        int base = ((q16 * 8 + grp) * 32 + gd * 4) * 4 + reg;
        Xs0[base + 0]  = xv.x;         // t=0 (k,k+1)
        Xs0[base + 4]  = xv.y;         // t=1
        Xs0[base + 8]  = xv.z;         // t=2
        Xs0[base + 12] = xv.w;         // t=3
    }

    int gc = 0;
    for (int L = 0; L < 6; L++) {
        const int sl = (L >= 3) ? (L - 3) : L;
        const uint32_t* XsIn = (sl == 0) ? Xs0 : Xs1;
        __half* Y = (L < 3) ? Ya : Yb;

        float acc[2][8][4];
#pragma unroll
        for (int mt = 0; mt < 2; mt++)
#pragma unroll
            for (int nt = 0; nt < 8; nt++)
#pragma unroll
                for (int r = 0; r < 4; r++) acc[mt][nt][r] = 0.f;

        for (int qc = 0; qc < 4; qc++, gc++) {
            cp_wait(23 - gc);
            __syncthreads();
            if (gc + 2 <= 23) {
                int nx = gc + 2;
                issueW(nx, nx % 3);
            }
            const uint32_t* Wb = Wc + (gc % 3) * 2048;
#pragma unroll
            for (int s = 0; s < 2; s++) {
                const int q16 = qc * 2 + s;
                uint32_t a[2][4];
#pragma unroll
                for (int mt = 0; mt < 2; mt++) {
                    uint4 av = *(const uint4*)(XsIn +
                        ((q16 * 8 + warp_m * 2 + mt) * 32 + lane) * 4);
                    a[mt][0] = av.x; a[mt][1] = av.y; a[mt][2] = av.z; a[mt][3] = av.w;
                }
                const uint32_t* Bb = Wb + s * 1024 + (warp_n * 4) * 128 + lane * 4;
#pragma unroll
                for (int ntp = 0; ntp < 4; ntp++) {
                    uint4 bb = *(const uint4*)(Bb + ntp * 128);
                    mma_f16(acc[0][2 * ntp],     a[0], bb.x, bb.y);
                    mma_f16(acc[0][2 * ntp + 1], a[0], bb.z, bb.w);
                    mma_f16(acc[1][2 * ntp],     a[1], bb.x, bb.y);
                    mma_f16(acc[1][2 * ntp + 1], a[1], bb.z, bb.w);
                }
            }
        }

        if (sl < 2) {
            if (sl == 1) __syncthreads();   // in-place on Xs1
#pragma unroll
            for (int mt = 0; mt < 2; mt++) {
#pragma unroll
                for (int nt = 0; nt < 8; nt++) {
                    int colL = warp_n * 64 + nt * 8 + thid * 2;
                    float b0 = sb[L * 128 + colL], b1 = sb[L * 128 + colL + 1];
                    float v00 = fmaxf(acc[mt][nt][0] + b0, 0.f);
                    float v01 = fmaxf(acc[mt][nt][1] + b1, 0.f);
                    float v10 = fmaxf(acc[mt][nt][2] + b0, 0.f);
                    float v11 = fmaxf(acc[mt][nt][3] + b1, 0.f);
                    int nq  = warp_n * 4 + (nt >> 1);
                    int kh8 = nt & 1;
                    int ngr = warp_m * 2 + mt;
                    int uidx = ((nq * 8 + ngr) * 32 + gid * 4 + thid) * 4;
                    Xs1[uidx + 2 * kh8]     = pk2h(v00, v01);
                    Xs1[uidx + 1 + 2 * kh8] = pk2h(v10, v11);
                }
            }
        } else {
#pragma unroll
            for (int mt = 0; mt < 2; mt++) {
                int rbase = row0 + warp_m * 32 + mt * 16 + gid;
#pragma unroll
                for (int nt = 0; nt < 8; nt++) {
                    int colL = warp_n * 64 + nt * 8 + thid * 2;
                    float b0 = sb[L * 128 + colL], b1 = sb[L * 128 + colL + 1];
                    uint32_t h01 = pk2h(fmaxf(acc[mt][nt][0] + b0, 0.f),
                                        fmaxf(acc[mt][nt][1] + b1, 0.f));
                    uint32_t h23 = pk2h(fmaxf(acc[mt][nt][2] + b0, 0.f),
                                        fmaxf(acc[mt][nt][3] + b1, 0.f));
                    if (rbase < N)     *(uint32_t*)(Y + (size_t)rbase * 128 + colL)       = h01;
                    if (rbase + 8 < N) *(uint32_t*)(Y + (size_t)(rbase + 8) * 128 + colL) = h23;
                }
            }
        }
    }
}

// ============ LSTM gate GEMM fp16, paired-B, 3-stage pipeline; writes c fp32 + c half ============
__global__ void __launch_bounds__(256, 2)
gemm_lstm(const __half* __restrict__ X1, const __half* __restrict__ X2,
          const __half* __restrict__ W1, const __half* __restrict__ W2,
          const float* __restrict__ pb,
          __half* __restrict__ hout, float* __restrict__ c,
          __half* __restrict__ ch, int N)
{
    extern __shared__ uint32_t smu[];
    uint32_t* Xs = smu;            // 3 * 2560
    uint32_t* Ws = smu + 3 * 2560; // 3 * 2048

    const int tid    = threadIdx.x;
    const int wid    = tid >> 5;
    const int lane   = tid & 31;
    const int warp_m = wid & 3;
    const int warp_n = wid >> 2;
    const int gid    = lane >> 2;
    const int thid   = lane & 3;
    const int colblk = blockIdx.x;            // 0..3 (fast dim -> L2-shared X)
    const int row0   = blockIdx.y << 7;
    const int col0   = colblk << 7;
    const int Q      = 8;

    const uint32_t xaddr = smem_u32(Xs);
    const uint32_t waddr = smem_u32(Ws);

    float acc[2][8][4];
#pragma unroll
    for (int mt = 0; mt < 2; mt++)
#pragma unroll
        for (int nt = 0; nt < 8; nt++)
#pragma unroll
            for (int r = 0; r < 4; r++) acc[mt][nt][r] = 0.f;

    auto issue = [&](int q, int st) {
        const int kc = q << 5;
        const uint32_t xb = xaddr + (uint32_t)st * 2560u * 4u;
        const uint32_t wb = waddr + (uint32_t)st * 2048u * 4u;
        const __half* Wl = (q < 4) ? W1 : W2;
        const int qa = q & 3;
#pragma unroll
        for (int it = 0; it < 4; it++) {
            int idx = it * 256 + tid;
            if (idx < 512) {
                int r  = idx >> 2;
                int c8 = idx & 3;
                int gk = kc + c8 * 8;
                int grow = row0 + r;
                const __half* xp = X1;
                int sz = 0;
                if (grow < N) {
                    xp = (gk < 128) ? (X1 + (size_t)grow * 128 + gk)
                                    : (X2 + (size_t)grow * 128 + (gk - 128));
                    sz = 16;
                }
                cp_async16(xb + (uint32_t)(r * 20 + c8 * 4) * 4u, xp, sz);
            } else {
                int j  = idx - 512;
                int s  = j >> 8;
                int j4 = j & 255;
                int q16 = qa * 2 + s;
                const __half* wp = Wl + (size_t)(q16 * 4096 + colblk * 1024 + j4 * 4) * 2;
                cp_async16(wb + (uint32_t)(s * 1024 + j4 * 4) * 4u, wp, 16);
            }
        }
        cp_commit();
    };

    issue(0, 0);
    issue(1, 1);
    for (int q = 0; q < Q; q++) {
        cp_wait(Q - 1 - q);
        __syncthreads();
        if (q + 2 < Q) issue(q + 2, (q + 2) % 3);

        const uint32_t* Xb = Xs + (q % 3) * 2560;
        const uint32_t* Wb = Ws + (q % 3) * 2048;
#pragma unroll
        for (int s = 0; s < 2; s++) {
            const int kbu = s * 8;
            uint32_t a[2][4];
#pragma unroll
            for (int mt = 0; mt < 2; mt++) {
                int rr = warp_m * 32 + mt * 16 + gid;
                a[mt][0] = Xb[rr * 20 + kbu + thid];
                a[mt][1] = Xb[(rr + 8) * 20 + kbu + thid];
                a[mt][2] = Xb[rr * 20 + kbu + 4 + thid];
                a[mt][3] = Xb[(rr + 8) * 20 + kbu + 4 + thid];
            }
            const uint32_t* Bb = Wb + s * 1024 + (warp_n * 4) * 128 + lane * 4;
#pragma unroll
            for (int ntp = 0; ntp < 4; ntp++) {
                uint4 bb = *(const uint4*)(Bb + ntp * 128);
                mma_f16(acc[0][2 * ntp],     a[0], bb.x, bb.y);
                mma_f16(acc[0][2 * ntp + 1], a[0], bb.z, bb.w);
                mma_f16(acc[1][2 * ntp],     a[1], bb.x, bb.y);
                mma_f16(acc[1][2 * ntp + 1], a[1], bb.z, bb.w);
            }
        }
    }

    // ---- fused LSTM epilogue ----
    // gate exchange: lanes thid/thid^1 (odd bit) swap (i,f)/(g,o);
    // c-half pairing: lanes thid/thid^2 hold feats f0/f0+1 of the same row.
    const bool odd = (lane & 1);
    const int featbase = (col0 + warp_n * 64) >> 2;
#pragma unroll
    for (int mt = 0; mt < 2; mt++) {
        int rbase = row0 + warp_m * 32 + mt * 16 + gid;
#pragma unroll
        for (int nt = 0; nt < 8; nt++) {
            int colL = warp_n * 64 + nt * 8 + thid * 2;
            float b0 = pb[col0 + colL], b1 = pb[col0 + colL + 1];
            float v00 = acc[mt][nt][0] + b0;
            float v01 = acc[mt][nt][1] + b1;
            float v10 = acc[mt][nt][2] + b0;
            float v11 = acc[mt][nt][3] + b1;
            float s0 = odd ? v00 : v10;
            float s1 = odd ? v01 : v11;
            float t0 = __shfl_xor_sync(0xFFFFFFFFu, s0, 1);
            float t1 = __shfl_xor_sync(0xFFFFFFFFu, s1, 1);
            float gi = odd ? t0 : v00;
            float gf = odd ? t1 : v01;
            float gg = odd ? v10 : t0;
            float go = odd ? v11 : t1;
            int row  = rbase + (odd ? 8 : 0);
            int feat = featbase + nt * 2 + (thid >> 1);
            float cp2 = (row < N) ? c[(size_t)row * 128 + feat] : 0.f;
            float cn = sigmoidf(gf) * cp2 + sigmoidf(gi) * tanhf(gg);
            float cr = fmaxf(cn, 0.f);
            // partner (thid^2) has feat+1 (or feat-1) of the SAME row
            float cpart = __shfl_xor_sync(0xFFFFFFFFu, cr, 2);
            if (row < N) {
                size_t o = (size_t)row * 128 + feat;
                hout[o] = __float2half_rn(sigmoidf(go) * tanhf(cn));
                c[o] = cr;
                if ((thid & 2) == 0) {   // holds even feat; partner holds feat+1
                    *(uint32_t*)(ch + (size_t)row * 128 + feat) = pk2h(cr, cpart);
                }
            }
        }
    }
}

// ---------------- CSR gather (half in/out, fp32 accumulate) ----------------
__global__ void gather2(const __half* __restrict__ ta, const int* __restrict__ offa,
                        const int* __restrict__ csra,
                        const __half* __restrict__ tb, const int* __restrict__ offb,
                        const int* __restrict__ csrb,
                        __half* __restrict__ m, int N)
{
    int gw   = (blockIdx.x * blockDim.x + threadIdx.x) >> 5;
    int lane = threadIdx.x & 31;
    if (gw >= N) return;
    float4 acc = make_float4(0.f, 0.f, 0.f, 0.f);
    int s0 = gw ? offa[gw - 1] : 0;
    int e0 = offa[gw];
    for (int e = s0; e < e0; e++) {
        int src = csra[e];
        uint2 raw = *(const uint2*)(ta + (size_t)src * 128 + lane * 4);
        float2 f0 = __half22float2(*(__half2*)&raw.x);
        float2 f1 = __half22float2(*(__half2*)&raw.y);
        acc.x += f0.x; acc.y += f0.y; acc.z += f1.x; acc.w += f1.y;
    }
    int s1 = gw ? offb[gw - 1] : 0;
    int e1 = offb[gw];
    for (int e = s1; e < e1; e++) {
        int src = csrb[e];
        uint2 raw = *(const uint2*)(tb + (size_t)src * 128 + lane * 4);
        float2 f0 = __half22float2(*(__half2*)&raw.x);
        float2 f1 = __half22float2(*(__half2*)&raw.y);
        acc.x += f0.x; acc.y += f0.y; acc.z += f1.x; acc.w += f1.y;
    }
    uint2 outv;
    outv.x = pk2h(acc.x, acc.y);
    outv.y = pk2h(acc.z, acc.w);
    *(uint2*)(m + (size_t)gw * 128 + lane * 4) = outv;
}

// ---------------- attention pooling ----------------
__global__ void pool_reset(unsigned* maxu, float* sum, float* red) {
    if (threadIdx.x == 0) { *maxu = 0u; *sum = 0.f; }
    if (threadIdx.x < HDIM) red[threadIdx.x] = 0.f;
}

__global__ void gate_logits(const float* __restrict__ cc, const float* __restrict__ gW,
                            const float* __restrict__ gb, float* __restrict__ z,
                            unsigned* __restrict__ maxu, int n)
{
    __shared__ float smax[8];
    int gw   = (blockIdx.x * blockDim.x + threadIdx.x) >> 5;
    int lane = threadIdx.x & 31;
    int wid  = threadIdx.x >> 5;
    float myz = -1e30f;
    if (gw < n) {
        float4 a = *(const float4*)(cc + (size_t)gw * HDIM + lane * 4);
        float4 b = *(const float4*)(gW + lane * 4);
        float p = a.x * b.x + a.y * b.y + a.z * b.z + a.w * b.w;
        p += __shfl_down_sync(0xFFFFFFFFu, p, 16);
        p += __shfl_down_sync(0xFFFFFFFFu, p, 8);
        p += __shfl_down_sync(0xFFFFFFFFu, p, 4);
        p += __shfl_down_sync(0xFFFFFFFFu, p, 2);
        p += __shfl_down_sync(0xFFFFFFFFu, p, 1);
        if (lane == 0) {
            myz = p + gb[0];
            z[gw] = myz;
        }
    }
    if (lane == 0) smax[wid] = myz;
    __syncthreads();
    if (threadIdx.x == 0) {
        float mx = smax[0];
#pragma unroll
        for (int w = 1; w < 8; w++) mx = fmaxf(mx, smax[w]);
        atomicMax(maxu, f2ord(mx));
    }
}

__global__ void softmax_accum(const float* __restrict__ cc, const float* __restrict__ z,
                              const unsigned* __restrict__ maxu,
                              float* __restrict__ sum, float* __restrict__ red, int n)
{
    int t = threadIdx.x;
    float zmax = ord2f(*maxu);
    int c0 = blockIdx.x * 64;
    float acc = 0.f, wsum = 0.f;
    for (int i = 0; i < 64; i++) {
        int c = c0 + i;
        if (c >= n) break;
        float w = expf(z[c] - zmax);
        acc  += w * cc[(size_t)c * HDIM + t];
        wsum += w;
    }
    atomicAdd(&red[t], acc);
    if (t == 0) atomicAdd(sum, wsum);
}

__global__ void final_mlp(const float* __restrict__ red, const float* __restrict__ sum,
                          const float* __restrict__ mW1, const float* __restrict__ mb1,
                          const float* __restrict__ mW2, const float* __restrict__ mb2,
                          const float* __restrict__ mW3, const float* __restrict__ mb3,
                          float* __restrict__ out)
{
    __shared__ float x0[HDIM], x1[HDIM], x2[HDIM];
    int t = threadIdx.x;
    x0[t] = red[t] / (*sum);
    __syncthreads();
    {
        float a = mb1[t];
        for (int k = 0; k < HDIM; k++) a = fmaf(x0[k], mW1[t * HDIM + k], a);
        x1[t] = fmaxf(a, 0.f);
    }
    __syncthreads();
    {
        float a = mb2[t];
        for (int k = 0; k < HDIM; k++) a = fmaf(x1[k], mW2[t * HDIM + k], a);
        x2[t] = fmaxf(a, 0.f);
    }
    __syncthreads();
    if (t < 2) {
        float a = mb3[t];
        for (int k = 0; k < HDIM; k++) a = fmaf(x2[k], mW3[t * HDIM + k], a);
        out[t] = a;
    }
}

// ---------------- host orchestration ----------------
#define MLP_SMEM  (23296 * 4)    // 93184 bytes  -> 2 CTAs/SM
#define LSTM_SMEM (13824 * 4)    // 55296 bytes  -> 2 CTAs/SM

static void build_csr(const int* src, const int* dst, int* off, int* csr,
                      int* cnt, int* part, int Ndst)
{
    cudaMemsetAsync(cnt, 0, (size_t)Ndst * sizeof(int));
    hist_k<<<(NEDG + 255) / 256, 256>>>(dst, cnt, NEDG);
    int NB = (Ndst + 1023) / 1024;
    scan1_k<<<NB, 1024>>>(cnt, off, part, Ndst);
    scan2_k<<<1, 512>>>(part, NB);
    scan3_k<<<NB, 1024>>>(off, part, Ndst);
    fill_k<<<(NEDG + 255) / 256, 256>>>(src, dst, off, csr, NEDG);
}

extern "C" void kernel_launch(void* const* d_in, const int* in_sizes, int n_in,
                              void* d_out, int out_size)
{
    const int*   var_x    = (const int*)  d_in[0];
    const int*   clause_x = (const int*)  d_in[1];
    const int*   pos_src  = (const int*)  d_in[2];
    const int*   pos_dst  = (const int*)  d_in[3];
    const int*   neg_src  = (const int*)  d_in[4];
    const int*   neg_dst  = (const int*)  d_in[5];
    const int*   posr_src = (const int*)  d_in[6];
    const int*   posr_dst = (const int*)  d_in[7];
    const int*   negr_src = (const int*)  d_in[8];
    const int*   negr_dst = (const int*)  d_in[9];
    const float* embed    = (const float*)d_in[10];
    const float* eW1      = (const float*)d_in[11];
    const float* eb1      = (const float*)d_in[12];
    const float* eW2      = (const float*)d_in[13];
    const float* eb2      = (const float*)d_in[14];
    const float* eW3      = (const float*)d_in[15];
    const float* eb3      = (const float*)d_in[16];
    const float* Wih      = (const float*)d_in[17];
    const float* Whh      = (const float*)d_in[18];
    const float* bih      = (const float*)d_in[19];
    const float* bhh      = (const float*)d_in[20];
    const float* gW       = (const float*)d_in[21];
    const float* gb       = (const float*)d_in[22];
    const float* mW1      = (const float*)d_in[23];
    const float* mb1      = (const float*)d_in[24];
    const float* mW2      = (const float*)d_in[25];
    const float* mb2      = (const float*)d_in[26];
    const float* mW3      = (const float*)d_in[27];
    const float* mb3      = (const float*)d_in[28];
    float* out = (float*)d_out;

    cudaFuncSetAttribute(mlp3_dual, cudaFuncAttributeMaxDynamicSharedMemorySize, MLP_SMEM);
    cudaFuncSetAttribute(gemm_lstm, cudaFuncAttributeMaxDynamicSharedMemorySize, LSTM_SMEM);

    __half *hv, *hv2, *hc, *hc2, *t1, *t2, *m, *wh, *cvh, *cch;
    float *cv, *cc, *z, *red, *sum, *pb;
    unsigned* maxu;
    int *off, *csr, *cnt, *part;
    cudaGetSymbolAddress((void**)&hv,   g_hv);
    cudaGetSymbolAddress((void**)&hv2,  g_hv2);
    cudaGetSymbolAddress((void**)&hc,   g_hc);
    cudaGetSymbolAddress((void**)&hc2,  g_hc2);
    cudaGetSymbolAddress((void**)&t1,   g_t1);
    cudaGetSymbolAddress((void**)&t2,   g_t2);
    cudaGetSymbolAddress((void**)&m,    g_m);
    cudaGetSymbolAddress((void**)&cvh,  g_cvh);
    cudaGetSymbolAddress((void**)&cch,  g_cch);
    cudaGetSymbolAddress((void**)&cv,   g_cv);
    cudaGetSymbolAddress((void**)&cc,   g_cc);
    cudaGetSymbolAddress((void**)&z,    g_z);
    cudaGetSymbolAddress((void**)&red,  g_red);
    cudaGetSymbolAddress((void**)&sum,  g_sum);
    cudaGetSymbolAddress((void**)&maxu, g_maxu);
    cudaGetSymbolAddress((void**)&wh,   g_wh);
    cudaGetSymbolAddress((void**)&pb,   g_pb);
    cudaGetSymbolAddress((void**)&off,  g_off);
    cudaGetSymbolAddress((void**)&csr,  g_csr);
    cudaGetSymbolAddress((void**)&cnt,  g_cnt);
    cudaGetSymbolAddress((void**)&part, g_part);

    int* off_e[4] = {off, off + NCLS, off + 2 * NCLS, off + 3 * NCLS};
    int* csr_e[4] = {csr, csr + NEDG, csr + 2 * NEDG, csr + 3 * NEDG};

    const __half* E1 = wh + OFFH_E1;
    const __half* E2 = wh + OFFH_E2;
    const __half* E3 = wh + OFFH_E3;
    const __half* WIH = wh + OFFH_WIH;
    const __half* WHH = wh + OFFH_WHH;

    const int vgrid = (NVAR + 127) / 128;   // 782
    const int cgrid = (NCLS + 127) / 128;   // 3125
    const int EB = 16384;                    // per-etype weight block (halfs)

    prep_all<<<(PREP_N + 255) / 256, 256>>>(eW1, eW2, eW3, Wih, Whh, bih, bhh, wh, pb);
    init_embed<<<(NVAR * HDIM + 255) / 256, 256>>>(var_x,    embed, hv, cv, cvh, NVAR);
    init_embed<<<(NCLS * HDIM + 255) / 256, 256>>>(clause_x, embed, hc, cc, cch, NCLS);

    __half* hcs[2] = {hc, hc2};
    __half* hvs[2] = {hv, hv2};
    int hci = 0, hvi = 0;

    for (int s = 0; s < NSTEPS; s++) {
        // ---- relation 0: var -> clause (etypes 0,1 fused) ----
        mlp3_dual<<<vgrid, 256, MLP_SMEM>>>(cvh,
            E1 + 0 * EB, E2 + 0 * EB, E3 + 0 * EB,
            E1 + 1 * EB, E2 + 1 * EB, E3 + 1 * EB,
            eb1 + 0 * HDIM, eb2 + 0 * HDIM, eb3 + 0 * HDIM,
            eb1 + 1 * HDIM, eb2 + 1 * HDIM, eb3 + 1 * HDIM,
            t1, t2, NVAR);
        if (s == 0) {
            build_csr(pos_src,  pos_dst,  off_e[0], csr_e[0], cnt, part, NCLS);
            build_csr(neg_src,  neg_dst,  off_e[1], csr_e[1], cnt, part, NCLS);
            build_csr(posr_src, posr_dst, off_e[2], csr_e[2], cnt, part, NVAR);
            build_csr(negr_src, negr_dst, off_e[3], csr_e[3], cnt, part, NVAR);
        }
        gather2<<<(NCLS * 32 + 255) / 256, 256>>>(t1, off_e[0], csr_e[0],
                                                  t2, off_e[1], csr_e[1], m, NCLS);
        {
            dim3 grid(4, cgrid);
            gemm_lstm<<<grid, 256, LSTM_SMEM>>>(m, hcs[hci], WIH, WHH, pb,
                                                hcs[hci ^ 1], cc, cch, NCLS);
            hci ^= 1;
        }

        // ---- relation 1: clause -> var (etypes 2,3 fused) ----
        mlp3_dual<<<cgrid, 256, MLP_SMEM>>>(cch,
            E1 + 2 * EB, E2 + 2 * EB, E3 + 2 * EB,
            E1 + 3 * EB, E2 + 3 * EB, E3 + 3 * EB,
            eb1 + 2 * HDIM, eb2 + 2 * HDIM, eb3 + 2 * HDIM,
            eb1 + 3 * HDIM, eb2 + 3 * HDIM, eb3 + 3 * HDIM,
            t1, t2, NCLS);
        gather2<<<(NVAR * 32 + 255) / 256, 256>>>(t1, off_e[2], csr_e[2],
                                                  t2, off_e[3], csr_e[3], m, NVAR);
        {
            dim3 grid(4, vgrid);
            gemm_lstm<<<grid, 256, LSTM_SMEM>>>(m, hvs[hvi], WIH + 65536, WHH + 65536,
                                                pb + 512, hvs[hvi ^ 1], cv, cvh, NVAR);
            hvi ^= 1;
        }
    }

    // ---- GlobalAttentionPooling + final MLP ----
    pool_reset<<<1, 128>>>(maxu, sum, red);
    gate_logits<<<(NCLS * 32 + 255) / 256, 256>>>(cc, gW, gb, z, maxu, NCLS);
    softmax_accum<<<(NCLS + 63) / 64, 128>>>(cc, z, maxu, sum, red, NCLS);
    final_mlp<<<1, 128>>>(red, sum, mW1, mb1, mW2, mb2, mW3, mb3, out);
}

// round 16
// speedup vs baseline: 1.0306x; 1.0306x over previous
#include <cuda_runtime.h>
#include <cuda_fp16.h>
#include <math.h>
#include <stdint.h>

#define NVAR   100000
#define NCLS   400000
#define NEDG   600000
#define HDIM   128
#define NSTEPS 9

// ---------------- scratch (device globals) ----------------
__device__ __align__(16) __half g_hv [NVAR * HDIM];
__device__ __align__(16) __half g_hv2[NVAR * HDIM];
__device__ __align__(16) __half g_hc [NCLS * HDIM];
__device__ __align__(16) __half g_hc2[NCLS * HDIM];
__device__ __align__(16) __half g_t1 [NCLS * HDIM];
__device__ __align__(16) __half g_t2 [NCLS * HDIM];
__device__ __align__(16) __half g_m  [NCLS * HDIM];
__device__ __align__(16) __half g_cvh[NVAR * HDIM];   // fp16 shadow of c_v (post-relu)
__device__ __align__(16) __half g_cch[NCLS * HDIM];   // fp16 shadow of c_c
__device__ float g_cv [NVAR * HDIM];
__device__ float g_cc [NCLS * HDIM];
__device__ float g_z  [NCLS];
__device__ float    g_red[HDIM];
__device__ float    g_sum;
__device__ unsigned g_maxu;
// fp16 PAIRED fragment-major weights: eW1 | eW2 | eW3 | Wih' | Whh'
#define OFFH_E1  0
#define OFFH_E2  65536
#define OFFH_E3  131072
#define OFFH_WIH 196608
#define OFFH_WHH 327680
#define WH_N     458752
__device__ __align__(16) __half g_wh[WH_N];
__device__ float g_pb[1024];
#define PREP_N  459776
// CSR
__device__ int g_off[4][NCLS];
__device__ int g_csr[4][NEDG];
__device__ int g_cnt[NCLS];
__device__ int g_part[512];

// ---------------- helpers ----------------
__device__ __forceinline__ unsigned f2ord(float f) {
    unsigned b = __float_as_uint(f);
    return (b & 0x80000000u) ? ~b : (b | 0x80000000u);
}
__device__ __forceinline__ float ord2f(unsigned u) {
    unsigned b = (u & 0x80000000u) ? (u ^ 0x80000000u) : ~u;
    return __uint_as_float(b);
}
__device__ __forceinline__ float sigmoidf(float x) { return 1.0f / (1.0f + expf(-x)); }

__device__ __forceinline__ uint32_t pk2h(float a, float b) {
    __half2 h = __floats2half2_rn(a, b);
    return *(uint32_t*)&h;
}
__device__ __forceinline__ uint32_t smem_u32(const void* p) {
    uint32_t a;
    asm("{ .reg .u64 t; cvta.to.shared.u64 t, %1; cvt.u32.u64 %0, t; }" : "=r"(a) : "l"(p));
    return a;
}
__device__ __forceinline__ void cp_async16(uint32_t dst, const void* src, int srcbytes) {
    asm volatile("cp.async.cg.shared.global [%0], [%1], 16, %2;"
                 :: "r"(dst), "l"(src), "r"(srcbytes) : "memory");
}
__device__ __forceinline__ void cp_commit() {
    asm volatile("cp.async.commit_group;" ::: "memory");
}
__device__ __forceinline__ void cp_wait(int rem) {
    if (rem >= 1) asm volatile("cp.async.wait_group 1;" ::: "memory");
    else          asm volatile("cp.async.wait_group 0;" ::: "memory");
}
__device__ __forceinline__ void mma_f16(float* c, const uint32_t* a, uint32_t b0, uint32_t b1) {
    asm volatile(
        "mma.sync.aligned.m16n8k16.row.col.f32.f16.f16.f32 "
        "{%0,%1,%2,%3}, {%4,%5,%6,%7}, {%8,%9}, {%0,%1,%2,%3};"
        : "+f"(c[0]), "+f"(c[1]), "+f"(c[2]), "+f"(c[3])
        : "r"(a[0]), "r"(a[1]), "r"(a[2]), "r"(a[3]), "r"(b0), "r"(b1));
}

// ---------------- fused weight prep: fp16 PAIRED fragment-major ----------------
__global__ void prep_all(const float* __restrict__ eW1, const float* __restrict__ eW2,
                         const float* __restrict__ eW3, const float* __restrict__ Wih,
                         const float* __restrict__ Whh, const float* __restrict__ bih,
                         const float* __restrict__ bhh,
                         __half* __restrict__ wh, float* __restrict__ pbo)
{
    int i = blockIdx.x * blockDim.x + threadIdx.x;
    if (i >= PREP_N) return;
    if (i < 196608) {               // eW1|eW2|eW3
        const float* src = (i < 65536) ? eW1 : (i < 131072) ? eW2 : eW3;
        int base = (i < 65536) ? OFFH_E1 : (i < 131072) ? OFFH_E2 : OFFH_E3;
        int j = i & 65535;
        int etype = j >> 14;
        int rem = j & 16383;
        int n = rem >> 7, k = rem & 127;
        int uidx = ((k >> 4) * 8 + (n >> 4)) * 128 + ((n & 7) * 4 + ((k & 7) >> 1)) * 4
                   + ((n >> 3) & 1) * 2 + ((k >> 3) & 1);
        wh[base + (etype << 14) + uidx * 2 + (k & 1)] = __float2half_rn(src[j]);
    } else if (i < 458752) {        // Wih' | Whh'
        int j = i - 196608;
        const float* src = (j < 131072) ? Wih : Whh;
        int base = (j < 131072) ? OFFH_WIH : OFFH_WHH;
        j &= 131071;
        int rel = j >> 16;
        int rem = j & 65535;
        int r_old = rem >> 7, k = rem & 127;
        int gate = r_old >> 7, f = r_old & 127;
        int rn = (f << 2) | gate;
        int uidx = ((k >> 4) * 32 + (rn >> 4)) * 128 + ((rn & 7) * 4 + ((k & 7) >> 1)) * 4
                   + ((rn >> 3) & 1) * 2 + ((k >> 3) & 1);
        wh[base + (rel << 16) + uidx * 2 + (k & 1)] = __float2half_rn(src[j]);
    } else {                        // permuted bias sum (fp32)
        int j = i - 458752;
        int rel = j >> 9;
        int r_old = j & 511;
        int gate = r_old >> 7, f = r_old & 127;
        pbo[(rel << 9) + (f << 2) + gate] = bih[j] + bhh[j];
    }
}

// ---------------- CSR build kernels ----------------
__global__ void hist_k(const int* __restrict__ dst, int* __restrict__ cnt, int E) {
    int i = blockIdx.x * blockDim.x + threadIdx.x;
    if (i < E) atomicAdd(&cnt[dst[i]], 1);
}
__global__ void scan1_k(const int* __restrict__ cnt, int* __restrict__ off,
                        int* __restrict__ part, int N) {
    __shared__ int s[1024];
    int i = blockIdx.x * 1024 + threadIdx.x;
    int v = (i < N) ? cnt[i] : 0;
    s[threadIdx.x] = v;
    __syncthreads();
    for (int d = 1; d < 1024; d <<= 1) {
        int t = (threadIdx.x >= d) ? s[threadIdx.x - d] : 0;
        __syncthreads();
        s[threadIdx.x] += t;
        __syncthreads();
    }
    if (i < N) off[i] = s[threadIdx.x] - v;
    if (threadIdx.x == 1023) part[blockIdx.x] = s[1023];
}
__global__ void scan2_k(int* __restrict__ part, int NB) {
    __shared__ int s[512];
    int v = (threadIdx.x < NB) ? part[threadIdx.x] : 0;
    s[threadIdx.x] = v;
    __syncthreads();
    for (int d = 1; d < 512; d <<= 1) {
        int t = (threadIdx.x >= d) ? s[threadIdx.x - d] : 0;
        __syncthreads();
        s[threadIdx.x] += t;
        __syncthreads();
    }
    if (threadIdx.x < NB) part[threadIdx.x] = s[threadIdx.x] - v;
}
__global__ void scan3_k(int* __restrict__ off, const int* __restrict__ part, int N) {
    int i = blockIdx.x * 1024 + threadIdx.x;
    if (i < N) off[i] += part[blockIdx.x];
}
__global__ void fill_k(const int* __restrict__ src, const int* __restrict__ dst,
                       int* __restrict__ off, int* __restrict__ csr, int E) {
    int i = blockIdx.x * blockDim.x + threadIdx.x;
    if (i >= E) return;
    int p = atomicAdd(&off[dst[i]], 1);
    csr[p] = src[i];
}

// ---------------- init ----------------
__global__ void init_embed(const int* __restrict__ x, const float* __restrict__ embed,
                           __half* __restrict__ h, float* __restrict__ c,
                           __half* __restrict__ ch, int n) {
    int i = blockIdx.x * blockDim.x + threadIdx.x;
    if (i >= n * HDIM) return;
    int node = i >> 7, col = i & 127;
    float v = embed[x[node] * HDIM + col];
    h[i]  = __float2half_rn(v);
    c[i]  = v;
    ch[i] = __float2half_rn(v);
}

// ============ DUAL-etype fused 3-layer MLP, fp16 IN, paired-B, 3-stage pipeline ============
__global__ void __launch_bounds__(256, 2)
mlp3_dual(const __half* __restrict__ X,
          const __half* __restrict__ Wa1, const __half* __restrict__ Wa2,
          const __half* __restrict__ Wa3,
          const __half* __restrict__ Wb1, const __half* __restrict__ Wb2,
          const __half* __restrict__ Wb3,
          const float* __restrict__ Ba1, const float* __restrict__ Ba2,
          const float* __restrict__ Ba3,
          const float* __restrict__ Bb1, const float* __restrict__ Bb2,
          const float* __restrict__ Bb3,
          __half* __restrict__ Ya, __half* __restrict__ Yb, int N)
{
    extern __shared__ uint32_t smu[];
    uint32_t* Xs0 = smu;                  // 8192
    uint32_t* Xs1 = smu + 8192;           // 8192
    uint32_t* Wc  = smu + 16384;          // 3*2048
    float*    sb  = (float*)(smu + 22528); // 768

    const int tid    = threadIdx.x;
    const int wid    = tid >> 5;
    const int lane   = tid & 31;
    const int warp_m = wid & 3;
    const int warp_n = wid >> 2;
    const int gid    = lane >> 2;
    const int thid   = lane & 3;
    const int row0   = blockIdx.x << 7;

    const uint32_t wcaddr = smem_u32(Wc);

    if (tid < 128) {
        sb[tid]       = Ba1[tid];
        sb[128 + tid] = Ba2[tid];
        sb[256 + tid] = Ba3[tid];
        sb[384 + tid] = Bb1[tid];
        sb[512 + tid] = Bb2[tid];
        sb[640 + tid] = Bb3[tid];
    }

    auto issueW = [&](int g, int st) {
        const __half* Wl =
            (g < 12) ? ((g < 4) ? Wa1 : (g < 8) ? Wa2 : Wa3)
                     : ((g < 16) ? Wb1 : (g < 20) ? Wb2 : Wb3);
        Wl += (size_t)(g & 3) * 4096;
#pragma unroll
        for (int it = 0; it < 2; it++) {
            int idx = it * 256 + tid;
            cp_async16(wcaddr + (uint32_t)(st * 2048 + idx * 4) * 4u, Wl + idx * 8, 16);
        }
        cp_commit();
    };

    issueW(0, 0);
    issueW(1, 1);

    // prologue: X (fp16 row-major) -> fragments in Xs0 (no conversion needed)
#pragma unroll
    for (int it = 0; it < 8; it++) {
        int idx = it * 256 + tid;      // 0..2047
        int r   = idx & 127;
        int c8  = idx >> 7;            // 0..15
        int gk  = c8 << 3;             // 8 halfs per load
        int grow = row0 + r;
        uint4 xv = make_uint4(0u, 0u, 0u, 0u);
        if (grow < N) xv = *(const uint4*)(X + (size_t)grow * 128 + gk);
        int q16 = gk >> 4;
        int kh8 = (gk >> 3) & 1;
        int grp = r >> 4;
        int gd  = r & 7;
        int mh  = (r >> 3) & 1;
        int reg = mh + 2 * kh8;
        int base = ((q16 * 8 + grp) * 32 + gd * 4) * 4 + reg;
        Xs0[base + 0]  = xv.x;
        Xs0[base + 4]  = xv.y;
        Xs0[base + 8]  = xv.z;
        Xs0[base + 12] = xv.w;
    }

    int gc = 0;
    for (int L = 0; L < 6; L++) {
        const int sl = (L >= 3) ? (L - 3) : L;
        const uint32_t* XsIn = (sl == 0) ? Xs0 : Xs1;
        __half* Y = (L < 3) ? Ya : Yb;

        float acc[2][8][4];
#pragma unroll
        for (int mt = 0; mt < 2; mt++)
#pragma unroll
            for (int nt = 0; nt < 8; nt++)
#pragma unroll
                for (int r = 0; r < 4; r++) acc[mt][nt][r] = 0.f;

        for (int qc = 0; qc < 4; qc++, gc++) {
            cp_wait(23 - gc);
            __syncthreads();
            if (gc + 2 <= 23) {
                int nx = gc + 2;
                issueW(nx, nx % 3);
            }
            const uint32_t* Wb = Wc + (gc % 3) * 2048;
#pragma unroll
            for (int s = 0; s < 2; s++) {
                const int q16 = qc * 2 + s;
                uint32_t a[2][4];
#pragma unroll
                for (int mt = 0; mt < 2; mt++) {
                    uint4 av = *(const uint4*)(XsIn +
                        ((q16 * 8 + warp_m * 2 + mt) * 32 + lane) * 4);
                    a[mt][0] = av.x; a[mt][1] = av.y; a[mt][2] = av.z; a[mt][3] = av.w;
                }
                const uint32_t* Bb = Wb + s * 1024 + (warp_n * 4) * 128 + lane * 4;
#pragma unroll
                for (int ntp = 0; ntp < 4; ntp++) {
                    uint4 bb = *(const uint4*)(Bb + ntp * 128);
                    mma_f16(acc[0][2 * ntp],     a[0], bb.x, bb.y);
                    mma_f16(acc[0][2 * ntp + 1], a[0], bb.z, bb.w);
                    mma_f16(acc[1][2 * ntp],     a[1], bb.x, bb.y);
                    mma_f16(acc[1][2 * ntp + 1], a[1], bb.z, bb.w);
                }
            }
        }

        if (sl < 2) {
            if (sl == 1) __syncthreads();   // in-place on Xs1
#pragma unroll
            for (int mt = 0; mt < 2; mt++) {
#pragma unroll
                for (int nt = 0; nt < 8; nt++) {
                    int colL = warp_n * 64 + nt * 8 + thid * 2;
                    float b0 = sb[L * 128 + colL], b1 = sb[L * 128 + colL + 1];
                    float v00 = fmaxf(acc[mt][nt][0] + b0, 0.f);
                    float v01 = fmaxf(acc[mt][nt][1] + b1, 0.f);
                    float v10 = fmaxf(acc[mt][nt][2] + b0, 0.f);
                    float v11 = fmaxf(acc[mt][nt][3] + b1, 0.f);
                    int nq  = warp_n * 4 + (nt >> 1);
                    int kh8 = nt & 1;
                    int ngr = warp_m * 2 + mt;
                    int uidx = ((nq * 8 + ngr) * 32 + gid * 4 + thid) * 4;
                    Xs1[uidx + 2 * kh8]     = pk2h(v00, v01);
                    Xs1[uidx + 1 + 2 * kh8] = pk2h(v10, v11);
                }
            }
        } else {
#pragma unroll
            for (int mt = 0; mt < 2; mt++) {
                int rbase = row0 + warp_m * 32 + mt * 16 + gid;
#pragma unroll
                for (int nt = 0; nt < 8; nt++) {
                    int colL = warp_n * 64 + nt * 8 + thid * 2;
                    float b0 = sb[L * 128 + colL], b1 = sb[L * 128 + colL + 1];
                    uint32_t h01 = pk2h(fmaxf(acc[mt][nt][0] + b0, 0.f),
                                        fmaxf(acc[mt][nt][1] + b1, 0.f));
                    uint32_t h23 = pk2h(fmaxf(acc[mt][nt][2] + b0, 0.f),
                                        fmaxf(acc[mt][nt][3] + b1, 0.f));
                    if (rbase < N)     *(uint32_t*)(Y + (size_t)rbase * 128 + colL)       = h01;
                    if (rbase + 8 < N) *(uint32_t*)(Y + (size_t)(rbase + 8) * 128 + colL) = h23;
                }
            }
        }
    }
}

// ============ LSTM gate GEMM fp16, paired-B, 3-stage pipeline ============
// Epilogue: h/c stores as in R14; c-half shadow staged through smem then
// written with coalesced uint4 stores (fixes R15's scattered-store regression).
__global__ void __launch_bounds__(256, 2)
gemm_lstm(const __half* __restrict__ X1, const __half* __restrict__ X2,
          const __half* __restrict__ W1, const __half* __restrict__ W2,
          const float* __restrict__ pb,
          __half* __restrict__ hout, float* __restrict__ c,
          __half* __restrict__ ch, int N)
{
    extern __shared__ uint32_t smu[];
    uint32_t* Xs = smu;            // 3 * 2560
    uint32_t* Ws = smu + 3 * 2560; // 3 * 2048

    const int tid    = threadIdx.x;
    const int wid    = tid >> 5;
    const int lane   = tid & 31;
    const int warp_m = wid & 3;
    const int warp_n = wid >> 2;
    const int gid    = lane >> 2;
    const int thid   = lane & 3;
    const int colblk = blockIdx.x;            // 0..3 (fast dim -> L2-shared X)
    const int row0   = blockIdx.y << 7;
    const int col0   = colblk << 7;
    const int Q      = 8;

    const uint32_t xaddr = smem_u32(Xs);
    const uint32_t waddr = smem_u32(Ws);

    float acc[2][8][4];
#pragma unroll
    for (int mt = 0; mt < 2; mt++)
#pragma unroll
        for (int nt = 0; nt < 8; nt++)
#pragma unroll
            for (int r = 0; r < 4; r++) acc[mt][nt][r] = 0.f;

    auto issue = [&](int q, int st) {
        const int kc = q << 5;
        const uint32_t xb = xaddr + (uint32_t)st * 2560u * 4u;
        const uint32_t wb = waddr + (uint32_t)st * 2048u * 4u;
        const __half* Wl = (q < 4) ? W1 : W2;
        const int qa = q & 3;
#pragma unroll
        for (int it = 0; it < 4; it++) {
            int idx = it * 256 + tid;
            if (idx < 512) {
                int r  = idx >> 2;
                int c8 = idx & 3;
                int gk = kc + c8 * 8;
                int grow = row0 + r;
                const __half* xp = X1;
                int sz = 0;
                if (grow < N) {
                    xp = (gk < 128) ? (X1 + (size_t)grow * 128 + gk)
                                    : (X2 + (size_t)grow * 128 + (gk - 128));
                    sz = 16;
                }
                cp_async16(xb + (uint32_t)(r * 20 + c8 * 4) * 4u, xp, sz);
            } else {
                int j  = idx - 512;
                int s  = j >> 8;
                int j4 = j & 255;
                int q16 = qa * 2 + s;
                const __half* wp = Wl + (size_t)(q16 * 4096 + colblk * 1024 + j4 * 4) * 2;
                cp_async16(wb + (uint32_t)(s * 1024 + j4 * 4) * 4u, wp, 16);
            }
        }
        cp_commit();
    };

    issue(0, 0);
    issue(1, 1);
    for (int q = 0; q < Q; q++) {
        cp_wait(Q - 1 - q);
        __syncthreads();
        if (q + 2 < Q) issue(q + 2, (q + 2) % 3);

        const uint32_t* Xb = Xs + (q % 3) * 2560;
        const uint32_t* Wb = Ws + (q % 3) * 2048;
#pragma unroll
        for (int s = 0; s < 2; s++) {
            const int kbu = s * 8;
            uint32_t a[2][4];
#pragma unroll
            for (int mt = 0; mt < 2; mt++) {
                int rr = warp_m * 32 + mt * 16 + gid;
                a[mt][0] = Xb[rr * 20 + kbu + thid];
                a[mt][1] = Xb[(rr + 8) * 20 + kbu + thid];
                a[mt][2] = Xb[rr * 20 + kbu + 4 + thid];
                a[mt][3] = Xb[(rr + 8) * 20 + kbu + 4 + thid];
            }
            const uint32_t* Bb = Wb + s * 1024 + (warp_n * 4) * 128 + lane * 4;
#pragma unroll
            for (int ntp = 0; ntp < 4; ntp++) {
                uint4 bb = *(const uint4*)(Bb + ntp * 128);
                mma_f16(acc[0][2 * ntp],     a[0], bb.x, bb.y);
                mma_f16(acc[0][2 * ntp + 1], a[0], bb.z, bb.w);
                mma_f16(acc[1][2 * ntp],     a[1], bb.x, bb.y);
                mma_f16(acc[1][2 * ntp + 1], a[1], bb.z, bb.w);
            }
        }
    }

    // ---- fused LSTM epilogue ----
    __syncthreads();                       // all mainloop smem reads done -> reuse as scr
    __half* scr = (__half*)smu;            // [128][40] halfs (rows 80B -> 16B aligned)
    const bool odd = (lane & 1);
    const int featbase = (col0 + warp_n * 64) >> 2;
#pragma unroll
    for (int mt = 0; mt < 2; mt++) {
        int rbase = row0 + warp_m * 32 + mt * 16 + gid;
#pragma unroll
        for (int nt = 0; nt < 8; nt++) {
            int colL = warp_n * 64 + nt * 8 + thid * 2;
            float b0 = pb[col0 + colL], b1 = pb[col0 + colL + 1];
            float v00 = acc[mt][nt][0] + b0;
            float v01 = acc[mt][nt][1] + b1;
            float v10 = acc[mt][nt][2] + b0;
            float v11 = acc[mt][nt][3] + b1;
            float s0 = odd ? v00 : v10;
            float s1 = odd ? v01 : v11;
            float t0 = __shfl_xor_sync(0xFFFFFFFFu, s0, 1);
            float t1 = __shfl_xor_sync(0xFFFFFFFFu, s1, 1);
            float gi = odd ? t0 : v00;
            float gf = odd ? t1 : v01;
            float gg = odd ? v10 : t0;
            float go = odd ? v11 : t1;
            int row  = rbase + (odd ? 8 : 0);
            int feat = featbase + nt * 2 + (thid >> 1);
            float cp2 = (row < N) ? c[(size_t)row * 128 + feat] : 0.f;
            float cn = sigmoidf(gf) * cp2 + sigmoidf(gi) * tanhf(gg);
            float cr = fmaxf(cn, 0.f);
            int rowL  = row - row0;
            int featL = warp_n * 16 + nt * 2 + (thid >> 1);
            scr[rowL * 40 + featL] = __float2half_rn(cr);
            if (row < N) {
                size_t o = (size_t)row * 128 + feat;
                hout[o] = __float2half_rn(sigmoidf(go) * tanhf(cn));
                c[o] = cr;
            }
        }
    }
    __syncthreads();
    // coalesced ch write: 128 rows x 32 halfs (4 x uint4 per row)
#pragma unroll
    for (int it = 0; it < 2; it++) {
        int idx = it * 256 + tid;          // 0..511
        int rowL = idx >> 2, seg = idx & 3;
        int row = row0 + rowL;
        if (row < N) {
            uint4 v = *(const uint4*)(scr + rowL * 40 + seg * 8);
            *(uint4*)(ch + (size_t)row * 128 + colblk * 32 + seg * 8) = v;
        }
    }
}

// ---------------- CSR gather (half in/out, fp32 accumulate) ----------------
__global__ void gather2(const __half* __restrict__ ta, const int* __restrict__ offa,
                        const int* __restrict__ csra,
                        const __half* __restrict__ tb, const int* __restrict__ offb,
                        const int* __restrict__ csrb,
                        __half* __restrict__ m, int N)
{
    int gw   = (blockIdx.x * blockDim.x + threadIdx.x) >> 5;
    int lane = threadIdx.x & 31;
    if (gw >= N) return;
    float4 acc = make_float4(0.f, 0.f, 0.f, 0.f);
    int s0 = gw ? offa[gw - 1] : 0;
    int e0 = offa[gw];
    for (int e = s0; e < e0; e++) {
        int src = csra[e];
        uint2 raw = *(const uint2*)(ta + (size_t)src * 128 + lane * 4);
        float2 f0 = __half22float2(*(__half2*)&raw.x);
        float2 f1 = __half22float2(*(__half2*)&raw.y);
        acc.x += f0.x; acc.y += f0.y; acc.z += f1.x; acc.w += f1.y;
    }
    int s1 = gw ? offb[gw - 1] : 0;
    int e1 = offb[gw];
    for (int e = s1; e < e1; e++) {
        int src = csrb[e];
        uint2 raw = *(const uint2*)(tb + (size_t)src * 128 + lane * 4);
        float2 f0 = __half22float2(*(__half2*)&raw.x);
        float2 f1 = __half22float2(*(__half2*)&raw.y);
        acc.x += f0.x; acc.y += f0.y; acc.z += f1.x; acc.w += f1.y;
    }
    uint2 outv;
    outv.x = pk2h(acc.x, acc.y);
    outv.y = pk2h(acc.z, acc.w);
    *(uint2*)(m + (size_t)gw * 128 + lane * 4) = outv;
}

// ---------------- attention pooling ----------------
__global__ void pool_reset(unsigned* maxu, float* sum, float* red) {
    if (threadIdx.x == 0) { *maxu = 0u; *sum = 0.f; }
    if (threadIdx.x < HDIM) red[threadIdx.x] = 0.f;
}

__global__ void gate_logits(const float* __restrict__ cc, const float* __restrict__ gW,
                            const float* __restrict__ gb, float* __restrict__ z,
                            unsigned* __restrict__ maxu, int n)
{
    __shared__ float smax[8];
    int gw   = (blockIdx.x * blockDim.x + threadIdx.x) >> 5;
    int lane = threadIdx.x & 31;
    int wid  = threadIdx.x >> 5;
    float myz = -1e30f;
    if (gw < n) {
        float4 a = *(const float4*)(cc + (size_t)gw * HDIM + lane * 4);
        float4 b = *(const float4*)(gW + lane * 4);
        float p = a.x * b.x + a.y * b.y + a.z * b.z + a.w * b.w;
        p += __shfl_down_sync(0xFFFFFFFFu, p, 16);
        p += __shfl_down_sync(0xFFFFFFFFu, p, 8);
        p += __shfl_down_sync(0xFFFFFFFFu, p, 4);
        p += __shfl_down_sync(0xFFFFFFFFu, p, 2);
        p += __shfl_down_sync(0xFFFFFFFFu, p, 1);
        if (lane == 0) {
            myz = p + gb[0];
            z[gw] = myz;
        }
    }
    if (lane == 0) smax[wid] = myz;
    __syncthreads();
    if (threadIdx.x == 0) {
        float mx = smax[0];
#pragma unroll
        for (int w = 1; w < 8; w++) mx = fmaxf(mx, smax[w]);
        atomicMax(maxu, f2ord(mx));
    }
}

__global__ void softmax_accum(const float* __restrict__ cc, const float* __restrict__ z,
                              const unsigned* __restrict__ maxu,
                              float* __restrict__ sum, float* __restrict__ red, int n)
{
    int t = threadIdx.x;
    float zmax = ord2f(*maxu);
    int c0 = blockIdx.x * 64;
    float acc = 0.f, wsum = 0.f;
    for (int i = 0; i < 64; i++) {
        int c = c0 + i;
        if (c >= n) break;
        float w = expf(z[c] - zmax);
        acc  += w * cc[(size_t)c * HDIM + t];
        wsum += w;
    }
    atomicAdd(&red[t], acc);
    if (t == 0) atomicAdd(sum, wsum);
}

__global__ void final_mlp(const float* __restrict__ red, const float* __restrict__ sum,
                          const float* __restrict__ mW1, const float* __restrict__ mb1,
                          const float* __restrict__ mW2, const float* __restrict__ mb2,
                          const float* __restrict__ mW3, const float* __restrict__ mb3,
                          float* __restrict__ out)
{
    __shared__ float x0[HDIM], x1[HDIM], x2[HDIM];
    int t = threadIdx.x;
    x0[t] = red[t] / (*sum);
    __syncthreads();
    {
        float a = mb1[t];
        for (int k = 0; k < HDIM; k++) a = fmaf(x0[k], mW1[t * HDIM + k], a);
        x1[t] = fmaxf(a, 0.f);
    }
    __syncthreads();
    {
        float a = mb2[t];
        for (int k = 0; k < HDIM; k++) a = fmaf(x1[k], mW2[t * HDIM + k], a);
        x2[t] = fmaxf(a, 0.f);
    }
    __syncthreads();
    if (t < 2) {
        float a = mb3[t];
        for (int k = 0; k < HDIM; k++) a = fmaf(x2[k], mW3[t * HDIM + k], a);
        out[t] = a;
    }
}

// ---------------- host orchestration ----------------
#define MLP_SMEM  (23296 * 4)    // 93184 bytes  -> 2 CTAs/SM
#define LSTM_SMEM (13824 * 4)    // 55296 bytes  -> 2 CTAs/SM

static void build_csr(const int* src, const int* dst, int* off, int* csr,
                      int* cnt, int* part, int Ndst)
{
    cudaMemsetAsync(cnt, 0, (size_t)Ndst * sizeof(int));
    hist_k<<<(NEDG + 255) / 256, 256>>>(dst, cnt, NEDG);
    int NB = (Ndst + 1023) / 1024;
    scan1_k<<<NB, 1024>>>(cnt, off, part, Ndst);
    scan2_k<<<1, 512>>>(part, NB);
    scan3_k<<<NB, 1024>>>(off, part, Ndst);
    fill_k<<<(NEDG + 255) / 256, 256>>>(src, dst, off, csr, NEDG);
}

extern "C" void kernel_launch(void* const* d_in, const int* in_sizes, int n_in,
                              void* d_out, int out_size)
{
    const int*   var_x    = (const int*)  d_in[0];
    const int*   clause_x = (const int*)  d_in[1];
    const int*   pos_src  = (const int*)  d_in[2];
    const int*   pos_dst  = (const int*)  d_in[3];
    const int*   neg_src  = (const int*)  d_in[4];
    const int*   neg_dst  = (const int*)  d_in[5];
    const int*   posr_src = (const int*)  d_in[6];
    const int*   posr_dst = (const int*)  d_in[7];
    const int*   negr_src = (const int*)  d_in[8];
    const int*   negr_dst = (const int*)  d_in[9];
    const float* embed    = (const float*)d_in[10];
    const float* eW1      = (const float*)d_in[11];
    const float* eb1      = (const float*)d_in[12];
    const float* eW2      = (const float*)d_in[13];
    const float* eb2      = (const float*)d_in[14];
    const float* eW3      = (const float*)d_in[15];
    const float* eb3      = (const float*)d_in[16];
    const float* Wih      = (const float*)d_in[17];
    const float* Whh      = (const float*)d_in[18];
    const float* bih      = (const float*)d_in[19];
    const float* bhh      = (const float*)d_in[20];
    const float* gW       = (const float*)d_in[21];
    const float* gb       = (const float*)d_in[22];
    const float* mW1      = (const float*)d_in[23];
    const float* mb1      = (const float*)d_in[24];
    const float* mW2      = (const float*)d_in[25];
    const float* mb2      = (const float*)d_in[26];
    const float* mW3      = (const float*)d_in[27];
    const float* mb3      = (const float*)d_in[28];
    float* out = (float*)d_out;

    cudaFuncSetAttribute(mlp3_dual, cudaFuncAttributeMaxDynamicSharedMemorySize, MLP_SMEM);
    cudaFuncSetAttribute(gemm_lstm, cudaFuncAttributeMaxDynamicSharedMemorySize, LSTM_SMEM);

    __half *hv, *hv2, *hc, *hc2, *t1, *t2, *m, *wh, *cvh, *cch;
    float *cv, *cc, *z, *red, *sum, *pb;
    unsigned* maxu;
    int *off, *csr, *cnt, *part;
    cudaGetSymbolAddress((void**)&hv,   g_hv);
    cudaGetSymbolAddress((void**)&hv2,  g_hv2);
    cudaGetSymbolAddress((void**)&hc,   g_hc);
    cudaGetSymbolAddress((void**)&hc2,  g_hc2);
    cudaGetSymbolAddress((void**)&t1,   g_t1);
    cudaGetSymbolAddress((void**)&t2,   g_t2);
    cudaGetSymbolAddress((void**)&m,    g_m);
    cudaGetSymbolAddress((void**)&cvh,  g_cvh);
    cudaGetSymbolAddress((void**)&cch,  g_cch);
    cudaGetSymbolAddress((void**)&cv,   g_cv);
    cudaGetSymbolAddress((void**)&cc,   g_cc);
    cudaGetSymbolAddress((void**)&z,    g_z);
    cudaGetSymbolAddress((void**)&red,  g_red);
    cudaGetSymbolAddress((void**)&sum,  g_sum);
    cudaGetSymbolAddress((void**)&maxu, g_maxu);
    cudaGetSymbolAddress((void**)&wh,   g_wh);
    cudaGetSymbolAddress((void**)&pb,   g_pb);
    cudaGetSymbolAddress((void**)&off,  g_off);
    cudaGetSymbolAddress((void**)&csr,  g_csr);
    cudaGetSymbolAddress((void**)&cnt,  g_cnt);
    cudaGetSymbolAddress((void**)&part, g_part);

    int* off_e[4] = {off, off + NCLS, off + 2 * NCLS, off + 3 * NCLS};
    int* csr_e[4] = {csr, csr + NEDG, csr + 2 * NEDG, csr + 3 * NEDG};

    const __half* E1 = wh + OFFH_E1;
    const __half* E2 = wh + OFFH_E2;
    const __half* E3 = wh + OFFH_E3;
    const __half* WIH = wh + OFFH_WIH;
    const __half* WHH = wh + OFFH_WHH;

    const int vgrid = (NVAR + 127) / 128;   // 782
    const int cgrid = (NCLS + 127) / 128;   // 3125
    const int EB = 16384;                    // per-etype weight block (halfs)

    prep_all<<<(PREP_N + 255) / 256, 256>>>(eW1, eW2, eW3, Wih, Whh, bih, bhh, wh, pb);
    init_embed<<<(NVAR * HDIM + 255) / 256, 256>>>(var_x,    embed, hv, cv, cvh, NVAR);
    init_embed<<<(NCLS * HDIM + 255) / 256, 256>>>(clause_x, embed, hc, cc, cch, NCLS);

    __half* hcs[2] = {hc, hc2};
    __half* hvs[2] = {hv, hv2};
    int hci = 0, hvi = 0;

    for (int s = 0; s < NSTEPS; s++) {
        // ---- relation 0: var -> clause (etypes 0,1 fused) ----
        mlp3_dual<<<vgrid, 256, MLP_SMEM>>>(cvh,
            E1 + 0 * EB, E2 + 0 * EB, E3 + 0 * EB,
            E1 + 1 * EB, E2 + 1 * EB, E3 + 1 * EB,
            eb1 + 0 * HDIM, eb2 + 0 * HDIM, eb3 + 0 * HDIM,
            eb1 + 1 * HDIM, eb2 + 1 * HDIM, eb3 + 1 * HDIM,
            t1, t2, NVAR);
        if (s == 0) {
            build_csr(pos_src,  pos_dst,  off_e[0], csr_e[0], cnt, part, NCLS);
            build_csr(neg_src,  neg_dst,  off_e[1], csr_e[1], cnt, part, NCLS);
            build_csr(posr_src, posr_dst, off_e[2], csr_e[2], cnt, part, NVAR);
            build_csr(negr_src, negr_dst, off_e[3], csr_e[3], cnt, part, NVAR);
        }
        gather2<<<(NCLS * 32 + 255) / 256, 256>>>(t1, off_e[0], csr_e[0],
                                                  t2, off_e[1], csr_e[1], m, NCLS);
        {
            dim3 grid(4, cgrid);
            gemm_lstm<<<grid, 256, LSTM_SMEM>>>(m, hcs[hci], WIH, WHH, pb,
                                                hcs[hci ^ 1], cc, cch, NCLS);
            hci ^= 1;
        }

        // ---- relation 1: clause -> var (etypes 2,3 fused) ----
        mlp3_dual<<<cgrid, 256, MLP_SMEM>>>(cch,
            E1 + 2 * EB, E2 + 2 * EB, E3 + 2 * EB,
            E1 + 3 * EB, E2 + 3 * EB, E3 + 3 * EB,
            eb1 + 2 * HDIM, eb2 + 2 * HDIM, eb3 + 2 * HDIM,
            eb1 + 3 * HDIM, eb2 + 3 * HDIM, eb3 + 3 * HDIM,
            t1, t2, NCLS);
        gather2<<<(NVAR * 32 + 255) / 256, 256>>>(t1, off_e[2], csr_e[2],
                                                  t2, off_e[3], csr_e[3], m, NVAR);
        {
            dim3 grid(4, vgrid);
            gemm_lstm<<<grid, 256, LSTM_SMEM>>>(m, hvs[hvi], WIH + 65536, WHH + 65536,
                                                pb + 512, hvs[hvi ^ 1], cv, cvh, NVAR);
            hvi ^= 1;
        }
    }

    // ---- GlobalAttentionPooling + final MLP ----
    pool_reset<<<1, 128>>>(maxu, sum, red);
    gate_logits<<<(NCLS * 32 + 255) / 256, 256>>>(cc, gW, gb, z, maxu, NCLS);
    softmax_accum<<<(NCLS + 63) / 64, 128>>>(cc, z, maxu, sum, red, NCLS);
    final_mlp<<<1, 128>>>(red, sum, mW1, mb1, mW2, mb2, mW3, mb3, out);
}

// round 17
// speedup vs baseline: 1.1381x; 1.1044x over previous
#include <cuda_runtime.h>
#include <cuda_fp16.h>
#include <math.h>
#include <stdint.h>

#define NVAR   100000
#define NCLS   400000
#define NEDG   600000
#define HDIM   128
#define NSTEPS 9

// ---------------- scratch (device globals) ----------------
__device__ __align__(16) __half g_hv [NVAR * HDIM];
__device__ __align__(16) __half g_hv2[NVAR * HDIM];
__device__ __align__(16) __half g_hc [NCLS * HDIM];
__device__ __align__(16) __half g_hc2[NCLS * HDIM];
__device__ __align__(16) __half g_t1 [NCLS * HDIM];
__device__ __align__(16) __half g_t2 [NCLS * HDIM];
__device__ __align__(16) __half g_m  [NCLS * HDIM];
__device__ float g_cv [NVAR * HDIM];
__device__ float g_cc [NCLS * HDIM];
__device__ float g_z  [NCLS];
__device__ float    g_red[HDIM];
__device__ float    g_sum;
__device__ unsigned g_maxu;
// fp16 PAIRED fragment-major weights: eW1 | eW2 | eW3 | Wih' | Whh'
#define OFFH_E1  0
#define OFFH_E2  65536
#define OFFH_E3  131072
#define OFFH_WIH 196608
#define OFFH_WHH 327680
#define WH_N     458752
__device__ __align__(16) __half g_wh[WH_N];
__device__ float g_pb[1024];
#define PREP_N  459776
// CSR
__device__ int g_off[4][NCLS];
__device__ int g_csr[4][NEDG];
__device__ int g_cnt[NCLS];
__device__ int g_part[512];

// ---------------- helpers ----------------
__device__ __forceinline__ unsigned f2ord(float f) {
    unsigned b = __float_as_uint(f);
    return (b & 0x80000000u) ? ~b : (b | 0x80000000u);
}
__device__ __forceinline__ float ord2f(unsigned u) {
    unsigned b = (u & 0x80000000u) ? (u ^ 0x80000000u) : ~u;
    return __uint_as_float(b);
}
__device__ __forceinline__ float sigmoidf(float x) { return 1.0f / (1.0f + expf(-x)); }

__device__ __forceinline__ uint32_t pk2h(float a, float b) {
    __half2 h = __floats2half2_rn(a, b);
    return *(uint32_t*)&h;
}
__device__ __forceinline__ uint32_t smem_u32(const void* p) {
    uint32_t a;
    asm("{ .reg .u64 t; cvta.to.shared.u64 t, %1; cvt.u32.u64 %0, t; }" : "=r"(a) : "l"(p));
    return a;
}
__device__ __forceinline__ void cp_async16(uint32_t dst, const void* src, int srcbytes) {
    asm volatile("cp.async.cg.shared.global [%0], [%1], 16, %2;"
                 :: "r"(dst), "l"(src), "r"(srcbytes) : "memory");
}
__device__ __forceinline__ void cp_commit() {
    asm volatile("cp.async.commit_group;" ::: "memory");
}
__device__ __forceinline__ void cp_wait(int rem) {
    if (rem >= 1) asm volatile("cp.async.wait_group 1;" ::: "memory");
    else          asm volatile("cp.async.wait_group 0;" ::: "memory");
}
__device__ __forceinline__ void mma_f16(float* c, const uint32_t* a, uint32_t b0, uint32_t b1) {
    asm volatile(
        "mma.sync.aligned.m16n8k16.row.col.f32.f16.f16.f32 "
        "{%0,%1,%2,%3}, {%4,%5,%6,%7}, {%8,%9}, {%0,%1,%2,%3};"
        : "+f"(c[0]), "+f"(c[1]), "+f"(c[2]), "+f"(c[3])
        : "r"(a[0]), "r"(a[1]), "r"(a[2]), "r"(a[3]), "r"(b0), "r"(b1));
}

// ---------------- fused weight prep: fp16 PAIRED fragment-major ----------------
__global__ void prep_all(const float* __restrict__ eW1, const float* __restrict__ eW2,
                         const float* __restrict__ eW3, const float* __restrict__ Wih,
                         const float* __restrict__ Whh, const float* __restrict__ bih,
                         const float* __restrict__ bhh,
                         __half* __restrict__ wh, float* __restrict__ pbo)
{
    int i = blockIdx.x * blockDim.x + threadIdx.x;
    if (i >= PREP_N) return;
    if (i < 196608) {               // eW1|eW2|eW3
        const float* src = (i < 65536) ? eW1 : (i < 131072) ? eW2 : eW3;
        int base = (i < 65536) ? OFFH_E1 : (i < 131072) ? OFFH_E2 : OFFH_E3;
        int j = i & 65535;
        int etype = j >> 14;
        int rem = j & 16383;
        int n = rem >> 7, k = rem & 127;
        int uidx = ((k >> 4) * 8 + (n >> 4)) * 128 + ((n & 7) * 4 + ((k & 7) >> 1)) * 4
                   + ((n >> 3) & 1) * 2 + ((k >> 3) & 1);
        wh[base + (etype << 14) + uidx * 2 + (k & 1)] = __float2half_rn(src[j]);
    } else if (i < 458752) {        // Wih' | Whh'
        int j = i - 196608;
        const float* src = (j < 131072) ? Wih : Whh;
        int base = (j < 131072) ? OFFH_WIH : OFFH_WHH;
        j &= 131071;
        int rel = j >> 16;
        int rem = j & 65535;
        int r_old = rem >> 7, k = rem & 127;
        int gate = r_old >> 7, f = r_old & 127;
        int rn = (f << 2) | gate;
        int uidx = ((k >> 4) * 32 + (rn >> 4)) * 128 + ((rn & 7) * 4 + ((k & 7) >> 1)) * 4
                   + ((rn >> 3) & 1) * 2 + ((k >> 3) & 1);
        wh[base + (rel << 16) + uidx * 2 + (k & 1)] = __float2half_rn(src[j]);
    } else {                        // permuted bias sum (fp32)
        int j = i - 458752;
        int rel = j >> 9;
        int r_old = j & 511;
        int gate = r_old >> 7, f = r_old & 127;
        pbo[(rel << 9) + (f << 2) + gate] = bih[j] + bhh[j];
    }
}

// ---------------- CSR build kernels ----------------
__global__ void hist_k(const int* __restrict__ dst, int* __restrict__ cnt, int E) {
    int i = blockIdx.x * blockDim.x + threadIdx.x;
    if (i < E) atomicAdd(&cnt[dst[i]], 1);
}
__global__ void scan1_k(const int* __restrict__ cnt, int* __restrict__ off,
                        int* __restrict__ part, int N) {
    __shared__ int s[1024];
    int i = blockIdx.x * 1024 + threadIdx.x;
    int v = (i < N) ? cnt[i] : 0;
    s[threadIdx.x] = v;
    __syncthreads();
    for (int d = 1; d < 1024; d <<= 1) {
        int t = (threadIdx.x >= d) ? s[threadIdx.x - d] : 0;
        __syncthreads();
        s[threadIdx.x] += t;
        __syncthreads();
    }
    if (i < N) off[i] = s[threadIdx.x] - v;
    if (threadIdx.x == 1023) part[blockIdx.x] = s[1023];
}
__global__ void scan2_k(int* __restrict__ part, int NB) {
    __shared__ int s[512];
    int v = (threadIdx.x < NB) ? part[threadIdx.x] : 0;
    s[threadIdx.x] = v;
    __syncthreads();
    for (int d = 1; d < 512; d <<= 1) {
        int t = (threadIdx.x >= d) ? s[threadIdx.x - d] : 0;
        __syncthreads();
        s[threadIdx.x] += t;
        __syncthreads();
    }
    if (threadIdx.x < NB) part[threadIdx.x] = s[threadIdx.x] - v;
}
__global__ void scan3_k(int* __restrict__ off, const int* __restrict__ part, int N) {
    int i = blockIdx.x * 1024 + threadIdx.x;
    if (i < N) off[i] += part[blockIdx.x];
}
__global__ void fill_k(const int* __restrict__ src, const int* __restrict__ dst,
                       int* __restrict__ off, int* __restrict__ csr, int E) {
    int i = blockIdx.x * blockDim.x + threadIdx.x;
    if (i >= E) return;
    int p = atomicAdd(&off[dst[i]], 1);
    csr[p] = src[i];
}

// ---------------- init ----------------
__global__ void init_embed(const int* __restrict__ x, const float* __restrict__ embed,
                           __half* __restrict__ h, float* __restrict__ c, int n) {
    int i = blockIdx.x * blockDim.x + threadIdx.x;
    if (i >= n * HDIM) return;
    int node = i >> 7, col = i & 127;
    float v = embed[x[node] * HDIM + col];
    h[i] = __float2half_rn(v);
    c[i] = v;
}

// ============ DUAL-etype fused 3-layer MLP, fp32 IN, paired-B, 3-stage pipeline ============
__global__ void __launch_bounds__(256, 2)
mlp3_dual(const float* __restrict__ X,
          const __half* __restrict__ Wa1, const __half* __restrict__ Wa2,
          const __half* __restrict__ Wa3,
          const __half* __restrict__ Wb1, const __half* __restrict__ Wb2,
          const __half* __restrict__ Wb3,
          const float* __restrict__ Ba1, const float* __restrict__ Ba2,
          const float* __restrict__ Ba3,
          const float* __restrict__ Bb1, const float* __restrict__ Bb2,
          const float* __restrict__ Bb3,
          __half* __restrict__ Ya, __half* __restrict__ Yb, int N)
{
    extern __shared__ uint32_t smu[];
    uint32_t* Xs0 = smu;                  // 8192
    uint32_t* Xs1 = smu + 8192;           // 8192
    uint32_t* Wc  = smu + 16384;          // 3*2048
    float*    sb  = (float*)(smu + 22528); // 768

    const int tid    = threadIdx.x;
    const int wid    = tid >> 5;
    const int lane   = tid & 31;
    const int warp_m = wid & 3;
    const int warp_n = wid >> 2;
    const int gid    = lane >> 2;
    const int thid   = lane & 3;
    const int row0   = blockIdx.x << 7;

    const uint32_t wcaddr = smem_u32(Wc);

    if (tid < 128) {
        sb[tid]       = Ba1[tid];
        sb[128 + tid] = Ba2[tid];
        sb[256 + tid] = Ba3[tid];
        sb[384 + tid] = Bb1[tid];
        sb[512 + tid] = Bb2[tid];
        sb[640 + tid] = Bb3[tid];
    }

    auto issueW = [&](int g, int st) {
        const __half* Wl =
            (g < 12) ? ((g < 4) ? Wa1 : (g < 8) ? Wa2 : Wa3)
                     : ((g < 16) ? Wb1 : (g < 20) ? Wb2 : Wb3);
        Wl += (size_t)(g & 3) * 4096;
#pragma unroll
        for (int it = 0; it < 2; it++) {
            int idx = it * 256 + tid;
            cp_async16(wcaddr + (uint32_t)(st * 2048 + idx * 4) * 4u, Wl + idx * 8, 16);
        }
        cp_commit();
    };

    issueW(0, 0);
    issueW(1, 1);

    // prologue: X (fp32) -> half2 fragments in Xs0
#pragma unroll
    for (int it = 0; it < 16; it++) {
        int idx = it * 256 + tid;
        int r   = idx & 127;
        int c4  = idx >> 7;
        int gk  = c4 << 2;
        int grow = row0 + r;
        float4 xv = make_float4(0.f, 0.f, 0.f, 0.f);
        if (grow < N) xv = *(const float4*)(X + (size_t)grow * 128 + gk);
        int q16 = gk >> 4;
        int grp = r >> 4;
        int gd  = r & 7;
        int mh  = (r >> 3) & 1;
        int kh8 = (gk >> 3) & 1;
        int t0  = (gk & 7) >> 1;
        int reg = mh + 2 * kh8;
        int base = ((q16 * 8 + grp) * 32 + gd * 4) * 4 + reg;
        Xs0[base + t0 * 4]       = pk2h(xv.x, xv.y);
        Xs0[base + (t0 + 1) * 4] = pk2h(xv.z, xv.w);
    }

    int gc = 0;
    for (int L = 0; L < 6; L++) {
        const int sl = (L >= 3) ? (L - 3) : L;
        const uint32_t* XsIn = (sl == 0) ? Xs0 : Xs1;
        __half* Y = (L < 3) ? Ya : Yb;

        float acc[2][8][4];
#pragma unroll
        for (int mt = 0; mt < 2; mt++)
#pragma unroll
            for (int nt = 0; nt < 8; nt++)
#pragma unroll
                for (int r = 0; r < 4; r++) acc[mt][nt][r] = 0.f;

        for (int qc = 0; qc < 4; qc++, gc++) {
            cp_wait(23 - gc);
            __syncthreads();
            if (gc + 2 <= 23) {
                int nx = gc + 2;
                issueW(nx, nx % 3);
            }
            const uint32_t* Wb = Wc + (gc % 3) * 2048;
#pragma unroll
            for (int s = 0; s < 2; s++) {
                const int q16 = qc * 2 + s;
                uint32_t a[2][4];
#pragma unroll
                for (int mt = 0; mt < 2; mt++) {
                    uint4 av = *(const uint4*)(XsIn +
                        ((q16 * 8 + warp_m * 2 + mt) * 32 + lane) * 4);
                    a[mt][0] = av.x; a[mt][1] = av.y; a[mt][2] = av.z; a[mt][3] = av.w;
                }
                const uint32_t* Bb = Wb + s * 1024 + (warp_n * 4) * 128 + lane * 4;
#pragma unroll
                for (int ntp = 0; ntp < 4; ntp++) {
                    uint4 bb = *(const uint4*)(Bb + ntp * 128);
                    mma_f16(acc[0][2 * ntp],     a[0], bb.x, bb.y);
                    mma_f16(acc[0][2 * ntp + 1], a[0], bb.z, bb.w);
                    mma_f16(acc[1][2 * ntp],     a[1], bb.x, bb.y);
                    mma_f16(acc[1][2 * ntp + 1], a[1], bb.z, bb.w);
                }
            }
        }

        if (sl < 2) {
            if (sl == 1) __syncthreads();   // in-place on Xs1
#pragma unroll
            for (int mt = 0; mt < 2; mt++) {
#pragma unroll
                for (int nt = 0; nt < 8; nt++) {
                    int colL = warp_n * 64 + nt * 8 + thid * 2;
                    float b0 = sb[L * 128 + colL], b1 = sb[L * 128 + colL + 1];
                    float v00 = fmaxf(acc[mt][nt][0] + b0, 0.f);
                    float v01 = fmaxf(acc[mt][nt][1] + b1, 0.f);
                    float v10 = fmaxf(acc[mt][nt][2] + b0, 0.f);
                    float v11 = fmaxf(acc[mt][nt][3] + b1, 0.f);
                    int nq  = warp_n * 4 + (nt >> 1);
                    int kh8 = nt & 1;
                    int ngr = warp_m * 2 + mt;
                    int uidx = ((nq * 8 + ngr) * 32 + gid * 4 + thid) * 4;
                    Xs1[uidx + 2 * kh8]     = pk2h(v00, v01);
                    Xs1[uidx + 1 + 2 * kh8] = pk2h(v10, v11);
                }
            }
        } else {
#pragma unroll
            for (int mt = 0; mt < 2; mt++) {
                int rbase = row0 + warp_m * 32 + mt * 16 + gid;
#pragma unroll
                for (int nt = 0; nt < 8; nt++) {
                    int colL = warp_n * 64 + nt * 8 + thid * 2;
                    float b0 = sb[L * 128 + colL], b1 = sb[L * 128 + colL + 1];
                    uint32_t h01 = pk2h(fmaxf(acc[mt][nt][0] + b0, 0.f),
                                        fmaxf(acc[mt][nt][1] + b1, 0.f));
                    uint32_t h23 = pk2h(fmaxf(acc[mt][nt][2] + b0, 0.f),
                                        fmaxf(acc[mt][nt][3] + b1, 0.f));
                    if (rbase < N)     *(uint32_t*)(Y + (size_t)rbase * 128 + colL)       = h01;
                    if (rbase + 8 < N) *(uint32_t*)(Y + (size_t)(rbase + 8) * 128 + colL) = h23;
                }
            }
        }
    }
}

// ============ LSTM gate GEMM fp16, paired-B, 3-stage pipeline ============
__global__ void __launch_bounds__(256, 2)
gemm_lstm(const __half* __restrict__ X1, const __half* __restrict__ X2,
          const __half* __restrict__ W1, const __half* __restrict__ W2,
          const float* __restrict__ pb,
          __half* __restrict__ hout, float* __restrict__ c, int N)
{
    extern __shared__ uint32_t smu[];
    uint32_t* Xs = smu;            // 3 * 2560
    uint32_t* Ws = smu + 3 * 2560; // 3 * 2048

    const int tid    = threadIdx.x;
    const int wid    = tid >> 5;
    const int lane   = tid & 31;
    const int warp_m = wid & 3;
    const int warp_n = wid >> 2;
    const int gid    = lane >> 2;
    const int thid   = lane & 3;
    const int colblk = blockIdx.x;            // 0..3 (fast dim -> L2-shared X)
    const int row0   = blockIdx.y << 7;
    const int col0   = colblk << 7;
    const int Q      = 8;

    const uint32_t xaddr = smem_u32(Xs);
    const uint32_t waddr = smem_u32(Ws);

    float acc[2][8][4];
#pragma unroll
    for (int mt = 0; mt < 2; mt++)
#pragma unroll
        for (int nt = 0; nt < 8; nt++)
#pragma unroll
            for (int r = 0; r < 4; r++) acc[mt][nt][r] = 0.f;

    auto issue = [&](int q, int st) {
        const int kc = q << 5;
        const uint32_t xb = xaddr + (uint32_t)st * 2560u * 4u;
        const uint32_t wb = waddr + (uint32_t)st * 2048u * 4u;
        const __half* Wl = (q < 4) ? W1 : W2;
        const int qa = q & 3;
#pragma unroll
        for (int it = 0; it < 4; it++) {
            int idx = it * 256 + tid;
            if (idx < 512) {
                int r  = idx >> 2;
                int c8 = idx & 3;
                int gk = kc + c8 * 8;
                int grow = row0 + r;
                const __half* xp = X1;
                int sz = 0;
                if (grow < N) {
                    xp = (gk < 128) ? (X1 + (size_t)grow * 128 + gk)
                                    : (X2 + (size_t)grow * 128 + (gk - 128));
                    sz = 16;
                }
                cp_async16(xb + (uint32_t)(r * 20 + c8 * 4) * 4u, xp, sz);
            } else {
                int j  = idx - 512;
                int s  = j >> 8;
                int j4 = j & 255;
                int q16 = qa * 2 + s;
                const __half* wp = Wl + (size_t)(q16 * 4096 + colblk * 1024 + j4 * 4) * 2;
                cp_async16(wb + (uint32_t)(s * 1024 + j4 * 4) * 4u, wp, 16);
            }
        }
        cp_commit();
    };

    issue(0, 0);
    issue(1, 1);
    for (int q = 0; q < Q; q++) {
        cp_wait(Q - 1 - q);
        __syncthreads();
        if (q + 2 < Q) issue(q + 2, (q + 2) % 3);

        const uint32_t* Xb = Xs + (q % 3) * 2560;
        const uint32_t* Wb = Ws + (q % 3) * 2048;
#pragma unroll
        for (int s = 0; s < 2; s++) {
            const int kbu = s * 8;
            uint32_t a[2][4];
#pragma unroll
            for (int mt = 0; mt < 2; mt++) {
                int rr = warp_m * 32 + mt * 16 + gid;
                a[mt][0] = Xb[rr * 20 + kbu + thid];
                a[mt][1] = Xb[(rr + 8) * 20 + kbu + thid];
                a[mt][2] = Xb[rr * 20 + kbu + 4 + thid];
                a[mt][3] = Xb[(rr + 8) * 20 + kbu + 4 + thid];
            }
            const uint32_t* Bb = Wb + s * 1024 + (warp_n * 4) * 128 + lane * 4;
#pragma unroll
            for (int ntp = 0; ntp < 4; ntp++) {
                uint4 bb = *(const uint4*)(Bb + ntp * 128);
                mma_f16(acc[0][2 * ntp],     a[0], bb.x, bb.y);
                mma_f16(acc[0][2 * ntp + 1], a[0], bb.z, bb.w);
                mma_f16(acc[1][2 * ntp],     a[1], bb.x, bb.y);
                mma_f16(acc[1][2 * ntp + 1], a[1], bb.z, bb.w);
            }
        }
    }

    // ---- fused LSTM epilogue ----
    const bool odd = (lane & 1);
    const int featbase = (col0 + warp_n * 64) >> 2;
#pragma unroll
    for (int mt = 0; mt < 2; mt++) {
        int rbase = row0 + warp_m * 32 + mt * 16 + gid;
#pragma unroll
        for (int nt = 0; nt < 8; nt++) {
            int colL = warp_n * 64 + nt * 8 + thid * 2;
            float b0 = pb[col0 + colL], b1 = pb[col0 + colL + 1];
            float v00 = acc[mt][nt][0] + b0;
            float v01 = acc[mt][nt][1] + b1;
            float v10 = acc[mt][nt][2] + b0;
            float v11 = acc[mt][nt][3] + b1;
            float s0 = odd ? v00 : v10;
            float s1 = odd ? v01 : v11;
            float t0 = __shfl_xor_sync(0xFFFFFFFFu, s0, 1);
            float t1 = __shfl_xor_sync(0xFFFFFFFFu, s1, 1);
            float gi = odd ? t0 : v00;
            float gf = odd ? t1 : v01;
            float gg = odd ? v10 : t0;
            float go = odd ? v11 : t1;
            int row  = rbase + (odd ? 8 : 0);
            int feat = featbase + nt * 2 + (thid >> 1);
            if (row < N) {
                size_t o = (size_t)row * 128 + feat;
                float cp = c[o];
                float cn = sigmoidf(gf) * cp + sigmoidf(gi) * tanhf(gg);
                hout[o] = __float2half_rn(sigmoidf(go) * tanhf(cn));
                c[o] = fmaxf(cn, 0.f);
            }
        }
    }
}

// ---------------- CSR gather (half in/out, fp32 accumulate) ----------------
__global__ void gather2(const __half* __restrict__ ta, const int* __restrict__ offa,
                        const int* __restrict__ csra,
                        const __half* __restrict__ tb, const int* __restrict__ offb,
                        const int* __restrict__ csrb,
                        __half* __restrict__ m, int N)
{
    int gw   = (blockIdx.x * blockDim.x + threadIdx.x) >> 5;
    int lane = threadIdx.x & 31;
    if (gw >= N) return;
    float4 acc = make_float4(0.f, 0.f, 0.f, 0.f);
    int s0 = gw ? offa[gw - 1] : 0;
    int e0 = offa[gw];
    for (int e = s0; e < e0; e++) {
        int src = csra[e];
        uint2 raw = *(const uint2*)(ta + (size_t)src * 128 + lane * 4);
        float2 f0 = __half22float2(*(__half2*)&raw.x);
        float2 f1 = __half22float2(*(__half2*)&raw.y);
        acc.x += f0.x; acc.y += f0.y; acc.z += f1.x; acc.w += f1.y;
    }
    int s1 = gw ? offb[gw - 1] : 0;
    int e1 = offb[gw];
    for (int e = s1; e < e1; e++) {
        int src = csrb[e];
        uint2 raw = *(const uint2*)(tb + (size_t)src * 128 + lane * 4);
        float2 f0 = __half22float2(*(__half2*)&raw.x);
        float2 f1 = __half22float2(*(__half2*)&raw.y);
        acc.x += f0.x; acc.y += f0.y; acc.z += f1.x; acc.w += f1.y;
    }
    uint2 outv;
    outv.x = pk2h(acc.x, acc.y);
    outv.y = pk2h(acc.z, acc.w);
    *(uint2*)(m + (size_t)gw * 128 + lane * 4) = outv;
}

// ---------------- attention pooling ----------------
__global__ void pool_reset(unsigned* maxu, float* sum, float* red) {
    if (threadIdx.x == 0) { *maxu = 0u; *sum = 0.f; }
    if (threadIdx.x < HDIM) red[threadIdx.x] = 0.f;
}

__global__ void gate_logits(const float* __restrict__ cc, const float* __restrict__ gW,
                            const float* __restrict__ gb, float* __restrict__ z,
                            unsigned* __restrict__ maxu, int n)
{
    __shared__ float smax[8];
    int gw   = (blockIdx.x * blockDim.x + threadIdx.x) >> 5;
    int lane = threadIdx.x & 31;
    int wid  = threadIdx.x >> 5;
    float myz = -1e30f;
    if (gw < n) {
        float4 a = *(const float4*)(cc + (size_t)gw * HDIM + lane * 4);
        float4 b = *(const float4*)(gW + lane * 4);
        float p = a.x * b.x + a.y * b.y + a.z * b.z + a.w * b.w;
        p += __shfl_down_sync(0xFFFFFFFFu, p, 16);
        p += __shfl_down_sync(0xFFFFFFFFu, p, 8);
        p += __shfl_down_sync(0xFFFFFFFFu, p, 4);
        p += __shfl_down_sync(0xFFFFFFFFu, p, 2);
        p += __shfl_down_sync(0xFFFFFFFFu, p, 1);
        if (lane == 0) {
            myz = p + gb[0];
            z[gw] = myz;
        }
    }
    if (lane == 0) smax[wid] = myz;
    __syncthreads();
    if (threadIdx.x == 0) {
        float mx = smax[0];
#pragma unroll
        for (int w = 1; w < 8; w++) mx = fmaxf(mx, smax[w]);
        atomicMax(maxu, f2ord(mx));
    }
}

__global__ void softmax_accum(const float* __restrict__ cc, const float* __restrict__ z,
                              const unsigned* __restrict__ maxu,
                              float* __restrict__ sum, float* __restrict__ red, int n)
{
    int t = threadIdx.x;
    float zmax = ord2f(*maxu);
    int c0 = blockIdx.x * 64;
    float acc = 0.f, wsum = 0.f;
    for (int i = 0; i < 64; i++) {
        int c = c0 + i;
        if (c >= n) break;
        float w = expf(z[c] - zmax);
        acc  += w * cc[(size_t)c * HDIM + t];
        wsum += w;
    }
    atomicAdd(&red[t], acc);
    if (t == 0) atomicAdd(sum, wsum);
}

__global__ void final_mlp(const float* __restrict__ red, const float* __restrict__ sum,
                          const float* __restrict__ mW1, const float* __restrict__ mb1,
                          const float* __restrict__ mW2, const float* __restrict__ mb2,
                          const float* __restrict__ mW3, const float* __restrict__ mb3,
                          float* __restrict__ out)
{
    __shared__ float x0[HDIM], x1[HDIM], x2[HDIM];
    int t = threadIdx.x;
    x0[t] = red[t] / (*sum);
    __syncthreads();
    {
        float a = mb1[t];
        for (int k = 0; k < HDIM; k++) a = fmaf(x0[k], mW1[t * HDIM + k], a);
        x1[t] = fmaxf(a, 0.f);
    }
    __syncthreads();
    {
        float a = mb2[t];
        for (int k = 0; k < HDIM; k++) a = fmaf(x1[k], mW2[t * HDIM + k], a);
        x2[t] = fmaxf(a, 0.f);
    }
    __syncthreads();
    if (t < 2) {
        float a = mb3[t];
        for (int k = 0; k < HDIM; k++) a = fmaf(x2[k], mW3[t * HDIM + k], a);
        out[t] = a;
    }
}

// ---------------- host orchestration ----------------
#define MLP_SMEM  (23296 * 4)    // 93184 bytes  -> 2 CTAs/SM
#define LSTM_SMEM (13824 * 4)    // 55296 bytes  -> 2 CTAs/SM

static void build_csr(const int* src, const int* dst, int* off, int* csr,
                      int* cnt, int* part, int Ndst)
{
    cudaMemsetAsync(cnt, 0, (size_t)Ndst * sizeof(int));
    hist_k<<<(NEDG + 255) / 256, 256>>>(dst, cnt, NEDG);
    int NB = (Ndst + 1023) / 1024;
    scan1_k<<<NB, 1024>>>(cnt, off, part, Ndst);
    scan2_k<<<1, 512>>>(part, NB);
    scan3_k<<<NB, 1024>>>(off, part, Ndst);
    fill_k<<<(NEDG + 255) / 256, 256>>>(src, dst, off, csr, NEDG);
}

extern "C" void kernel_launch(void* const* d_in, const int* in_sizes, int n_in,
                              void* d_out, int out_size)
{
    const int*   var_x    = (const int*)  d_in[0];
    const int*   clause_x = (const int*)  d_in[1];
    const int*   pos_src  = (const int*)  d_in[2];
    const int*   pos_dst  = (const int*)  d_in[3];
    const int*   neg_src  = (const int*)  d_in[4];
    const int*   neg_dst  = (const int*)  d_in[5];
    const int*   posr_src = (const int*)  d_in[6];
    const int*   posr_dst = (const int*)  d_in[7];
    const int*   negr_src = (const int*)  d_in[8];
    const int*   negr_dst = (const int*)  d_in[9];
    const float* embed    = (const float*)d_in[10];
    const float* eW1      = (const float*)d_in[11];
    const float* eb1      = (const float*)d_in[12];
    const float* eW2      = (const float*)d_in[13];
    const float* eb2      = (const float*)d_in[14];
    const float* eW3      = (const float*)d_in[15];
    const float* eb3      = (const float*)d_in[16];
    const float* Wih      = (const float*)d_in[17];
    const float* Whh      = (const float*)d_in[18];
    const float* bih      = (const float*)d_in[19];
    const float* bhh      = (const float*)d_in[20];
    const float* gW       = (const float*)d_in[21];
    const float* gb       = (const float*)d_in[22];
    const float* mW1      = (const float*)d_in[23];
    const float* mb1      = (const float*)d_in[24];
    const float* mW2      = (const float*)d_in[25];
    const float* mb2      = (const float*)d_in[26];
    const float* mW3      = (const float*)d_in[27];
    const float* mb3      = (const float*)d_in[28];
    float* out = (float*)d_out;

    cudaFuncSetAttribute(mlp3_dual, cudaFuncAttributeMaxDynamicSharedMemorySize, MLP_SMEM);
    cudaFuncSetAttribute(gemm_lstm, cudaFuncAttributeMaxDynamicSharedMemorySize, LSTM_SMEM);

    __half *hv, *hv2, *hc, *hc2, *t1, *t2, *m, *wh;
    float *cv, *cc, *z, *red, *sum, *pb;
    unsigned* maxu;
    int *off, *csr, *cnt, *part;
    cudaGetSymbolAddress((void**)&hv,   g_hv);
    cudaGetSymbolAddress((void**)&hv2,  g_hv2);
    cudaGetSymbolAddress((void**)&hc,   g_hc);
    cudaGetSymbolAddress((void**)&hc2,  g_hc2);
    cudaGetSymbolAddress((void**)&t1,   g_t1);
    cudaGetSymbolAddress((void**)&t2,   g_t2);
    cudaGetSymbolAddress((void**)&m,    g_m);
    cudaGetSymbolAddress((void**)&cv,   g_cv);
    cudaGetSymbolAddress((void**)&cc,   g_cc);
    cudaGetSymbolAddress((void**)&z,    g_z);
    cudaGetSymbolAddress((void**)&red,  g_red);
    cudaGetSymbolAddress((void**)&sum,  g_sum);
    cudaGetSymbolAddress((void**)&maxu, g_maxu);
    cudaGetSymbolAddress((void**)&wh,   g_wh);
    cudaGetSymbolAddress((void**)&pb,   g_pb);
    cudaGetSymbolAddress((void**)&off,  g_off);
    cudaGetSymbolAddress((void**)&csr,  g_csr);
    cudaGetSymbolAddress((void**)&cnt,  g_cnt);
    cudaGetSymbolAddress((void**)&part, g_part);

    int* off_e[4] = {off, off + NCLS, off + 2 * NCLS, off + 3 * NCLS};
    int* csr_e[4] = {csr, csr + NEDG, csr + 2 * NEDG, csr + 3 * NEDG};

    const __half* E1 = wh + OFFH_E1;
    const __half* E2 = wh + OFFH_E2;
    const __half* E3 = wh + OFFH_E3;
    const __half* WIH = wh + OFFH_WIH;
    const __half* WHH = wh + OFFH_WHH;

    const int vgrid = (NVAR + 127) / 128;   // 782
    const int cgrid = (NCLS + 127) / 128;   // 3125
    const int EB = 16384;                    // per-etype weight block (halfs)

    prep_all<<<(PREP_N + 255) / 256, 256>>>(eW1, eW2, eW3, Wih, Whh, bih, bhh, wh, pb);
    init_embed<<<(NVAR * HDIM + 255) / 256, 256>>>(var_x,    embed, hv, cv, NVAR);
    init_embed<<<(NCLS * HDIM + 255) / 256, 256>>>(clause_x, embed, hc, cc, NCLS);

    __half* hcs[2] = {hc, hc2};
    __half* hvs[2] = {hv, hv2};
    int hci = 0, hvi = 0;

    for (int s = 0; s < NSTEPS; s++) {
        // ---- relation 0: var -> clause (etypes 0,1 fused) ----
        mlp3_dual<<<vgrid, 256, MLP_SMEM>>>(cv,
            E1 + 0 * EB, E2 + 0 * EB, E3 + 0 * EB,
            E1 + 1 * EB, E2 + 1 * EB, E3 + 1 * EB,
            eb1 + 0 * HDIM, eb2 + 0 * HDIM, eb3 + 0 * HDIM,
            eb1 + 1 * HDIM, eb2 + 1 * HDIM, eb3 + 1 * HDIM,
            t1, t2, NVAR);
        if (s == 0) {
            build_csr(pos_src,  pos_dst,  off_e[0], csr_e[0], cnt, part, NCLS);
            build_csr(neg_src,  neg_dst,  off_e[1], csr_e[1], cnt, part, NCLS);
            build_csr(posr_src, posr_dst, off_e[2], csr_e[2], cnt, part, NVAR);
            build_csr(negr_src, negr_dst, off_e[3], csr_e[3], cnt, part, NVAR);
        }
        gather2<<<(NCLS * 32 + 255) / 256, 256>>>(t1, off_e[0], csr_e[0],
                                                  t2, off_e[1], csr_e[1], m, NCLS);
        {
            dim3 grid(4, cgrid);
            gemm_lstm<<<grid, 256, LSTM_SMEM>>>(m, hcs[hci], WIH, WHH, pb,
                                                hcs[hci ^ 1], cc, NCLS);
            hci ^= 1;
        }

        // ---- relation 1: clause -> var (etypes 2,3 fused) ----
        mlp3_dual<<<cgrid, 256, MLP_SMEM>>>(cc,
            E1 + 2 * EB, E2 + 2 * EB, E3 + 2 * EB,
            E1 + 3 * EB, E2 + 3 * EB, E3 + 3 * EB,
            eb1 + 2 * HDIM, eb2 + 2 * HDIM, eb3 + 2 * HDIM,
            eb1 + 3 * HDIM, eb2 + 3 * HDIM, eb3 + 3 * HDIM,
            t1, t2, NCLS);
        gather2<<<(NVAR * 32 + 255) / 256, 256>>>(t1, off_e[2], csr_e[2],
                                                  t2, off_e[3], csr_e[3], m, NVAR);
        {
            dim3 grid(4, vgrid);
            gemm_lstm<<<grid, 256, LSTM_SMEM>>>(m, hvs[hvi], WIH + 65536, WHH + 65536,
                                                pb + 512, hvs[hvi ^ 1], cv, NVAR);
            hvi ^= 1;
        }
    }

    // ---- GlobalAttentionPooling + final MLP ----
    pool_reset<<<1, 128>>>(maxu, sum, red);
    gate_logits<<<(NCLS * 32 + 255) / 256, 256>>>(cc, gW, gb, z, maxu, NCLS);
    softmax_accum<<<(NCLS + 63) / 64, 128>>>(cc, z, maxu, sum, red, NCLS);
    final_mlp<<<1, 128>>>(red, sum, mW1, mb1, mW2, mb2, mW3, mb3, out);
}